// round 9
// baseline (speedup 1.0000x reference)
#include <cuda_runtime.h>
#include <mma.h>
#include <cstdint>

using namespace nvcuda;

#define B_  4
#define S_  2048
#define D_  1024
#define H_  16
#define DK_ 64

__device__ float g_Q [(size_t)B_*S_*D_];
__device__ float g_K [(size_t)B_*S_*D_];
__device__ float g_V [(size_t)B_*S_*D_];
__device__ float g_AO[(size_t)B_*S_*D_];

#define TF32(x) wmma::__float_to_tf32(x)

__device__ __forceinline__ void cpasync16(uint32_t saddr, const float* g) {
    asm volatile("cp.async.cg.shared.global [%0], [%1], 16;" :: "r"(saddr), "l"(g));
}
__device__ __forceinline__ void cpasync_commit() {
    asm volatile("cp.async.commit_group;");
}
__device__ __forceinline__ void cpasync_wait0() {
    asm volatile("cp.async.wait_group 0;");
}

// ---------------------------------------------------------------------------
// R4-proven tf32 NT GEMM body: C = A @ B^T + bias, 1024-dim fixed.
// BM=BN=128, BK=32, single-buffer, 256 thr, warp tile 64x32, 128 regs.
// ---------------------------------------------------------------------------
#define LDP 36

template<int ROUND>
__device__ __forceinline__ void gemm_body(
    const float* __restrict__ A, const float* __restrict__ Bm,
    const float* __restrict__ bias, float* __restrict__ C,
    float* As, float* Bs, float* Cs)
{
    const int tid  = threadIdx.x;
    const int w    = tid >> 5, lane = tid & 31;
    const int wm   = w >> 2, wn = w & 3;
    const size_t m0 = (size_t)blockIdx.y * 128;
    const size_t n0 = (size_t)blockIdx.x * 128;

    wmma::fragment<wmma::accumulator, 16, 16, 8, float> c[4][2];
#pragma unroll
    for (int i = 0; i < 4; i++)
#pragma unroll
        for (int j = 0; j < 2; j++) wmma::fill_fragment(c[i][j], 0.f);

    for (int k0 = 0; k0 < 1024; k0 += 32) {
        float4 av[4], bv[4];
#pragma unroll
        for (int it = 0; it < 4; it++) {
            int idx = tid + 256 * it;
            int row = idx >> 3, c4 = idx & 7;
            av[it] = *(const float4*)(A  + (m0 + row) * 1024 + k0 + c4 * 4);
            bv[it] = *(const float4*)(Bm + (n0 + row) * 1024 + k0 + c4 * 4);
        }
        __syncthreads();
#pragma unroll
        for (int it = 0; it < 4; it++) {
            int idx = tid + 256 * it;
            int row = idx >> 3, c4 = idx & 7;
            float4 a = av[it], b = bv[it];
            a.x = TF32(a.x); a.y = TF32(a.y); a.z = TF32(a.z); a.w = TF32(a.w);
            b.x = TF32(b.x); b.y = TF32(b.y); b.z = TF32(b.z); b.w = TF32(b.w);
            *(float4*)&As[row * LDP + c4 * 4] = a;
            *(float4*)&Bs[row * LDP + c4 * 4] = b;
        }
        __syncthreads();

#pragma unroll
        for (int ks = 0; ks < 4; ks++) {
            wmma::fragment<wmma::matrix_a, 16, 16, 8, wmma::precision::tf32, wmma::row_major> a[4];
            wmma::fragment<wmma::matrix_b, 16, 16, 8, wmma::precision::tf32, wmma::col_major> b[2];
#pragma unroll
            for (int i = 0; i < 4; i++)
                wmma::load_matrix_sync(a[i], &As[(64 * wm + 16 * i) * LDP + ks * 8], LDP);
#pragma unroll
            for (int j = 0; j < 2; j++)
                wmma::load_matrix_sync(b[j], &Bs[(32 * wn + 16 * j) * LDP + ks * 8], LDP);
#pragma unroll
            for (int i = 0; i < 4; i++)
#pragma unroll
                for (int j = 0; j < 2; j++)
                    wmma::mma_sync(c[i][j], a[i], b[j], c[i][j]);
        }
        __syncthreads();
    }

    float* buf = Cs + w * 320;
#pragma unroll
    for (int i = 0; i < 4; i++) {
#pragma unroll
        for (int j = 0; j < 2; j++) {
            wmma::store_matrix_sync(buf, c[i][j], 20, wmma::mem_row_major);
            __syncwarp();
            const int rr = lane >> 1, ch = (lane & 1) * 8;
            const size_t gr = m0 + 64 * wm + 16 * i + rr;
            const size_t gc = n0 + 32 * wn + 16 * j + ch;
            float4 v0 = *(float4*)&buf[rr * 20 + ch];
            float4 v1 = *(float4*)&buf[rr * 20 + ch + 4];
            v0.x += bias[gc + 0]; v0.y += bias[gc + 1];
            v0.z += bias[gc + 2]; v0.w += bias[gc + 3];
            v1.x += bias[gc + 4]; v1.y += bias[gc + 5];
            v1.z += bias[gc + 6]; v1.w += bias[gc + 7];
            if (ROUND) {
                v0.x = TF32(v0.x); v0.y = TF32(v0.y); v0.z = TF32(v0.z); v0.w = TF32(v0.w);
                v1.x = TF32(v1.x); v1.y = TF32(v1.y); v1.z = TF32(v1.z); v1.w = TF32(v1.w);
            }
            *(float4*)(C + gr * 1024 + gc)     = v0;
            *(float4*)(C + gr * 1024 + gc + 4) = v1;
            __syncwarp();
        }
    }
}

#define GEMM_SMEM_FLOATS (128 * LDP * 2 + 8 * 320)

__global__ __launch_bounds__(256) void qkv_proj(
    const float* __restrict__ q,  const float* __restrict__ k,
    const float* __restrict__ v,
    const float* __restrict__ Wq, const float* __restrict__ bq,
    const float* __restrict__ Wk, const float* __restrict__ bk,
    const float* __restrict__ Wv, const float* __restrict__ bv,
    float* __restrict__ Qo, float* __restrict__ Ko, float* __restrict__ Vo)
{
    __shared__ float smem[GEMM_SMEM_FLOATS];
    float* As = smem;
    float* Bs = smem + 128 * LDP;
    float* Cs = smem + 256 * LDP;
    const float *A, *W, *bi; float* C;
    if (blockIdx.z == 0)      { A = q; W = Wq; bi = bq; C = Qo; }
    else if (blockIdx.z == 1) { A = k; W = Wk; bi = bk; C = Ko; }
    else                      { A = v; W = Wv; bi = bv; C = Vo; }
    gemm_body<1>(A, W, bi, C, As, Bs, Cs);
}

__global__ __launch_bounds__(256) void out_proj(
    const float* __restrict__ A, const float* __restrict__ W,
    const float* __restrict__ bi, float* __restrict__ C)
{
    __shared__ float smem[GEMM_SMEM_FLOATS];
    gemm_body<0>(A, W, bi, C, smem, smem + 128 * LDP, smem + 256 * LDP);
}

// ---------------------------------------------------------------------------
// Fused attention, q-tile 256 rows, 512 threads (16 warps, grid 8x2).
// Per 64-wide k-chunk: S = Q Kc^T (Q frags in regs), exp in frags -> Ps,
// PV mma, then P gmem write + rowsums (overlaps tensor drain).
// Tail: thread-local P rescale, O staging, AO write.
// Smem (floats): Ps 256*72 @0, K dbl @18432, V dbl @27648. 147456 B, 1 CTA/SM.
// ---------------------------------------------------------------------------
#define QR 256
#define FA_SMEM_BYTES  (36864 * 4)
#define KB_OFF 18432
#define VB_OFF 27648
#define KVSTRIDE 4608

__global__ __launch_bounds__(512, 1) void fused_attn(
    const float* __restrict__ Q, const float* __restrict__ K,
    const float* __restrict__ V, float* __restrict__ P,
    float* __restrict__ AO)
{
    extern __shared__ float sm[];
    float* Ps = sm;
    const uint32_t smem_u32 = (uint32_t)__cvta_generic_to_shared(sm);

    const int tid = threadIdx.x, w = tid >> 5;
    const int wm = w >> 1, wn = w & 1;          // 8 x 2 warp grid
    const int bh = blockIdx.y, b = bh >> 4, h = bh & 15;
    const int q0 = blockIdx.x * QR;
    const int prow = tid >> 4;                  // 0..31
    const int pc4  = tid & 15;

    const float* Qb = Q + (size_t)b * S_ * D_ + h * DK_;
    const float* Kb = K + (size_t)b * S_ * D_ + h * DK_;
    const float* Vb = V + (size_t)b * S_ * D_ + h * DK_;
    float* Pb = P + (size_t)bh * S_ * S_;

    // ---- Stage Q tile [256x64] -> Ps, preload register fragments ----
#pragma unroll
    for (int it = 0; it < 8; it++) {
        int idx = tid + 512 * it;               // 0..4095
        int row = idx >> 4, c4 = idx & 15;
        *(float4*)&Ps[row * 72 + c4 * 4] =
            *(const float4*)(Qb + (size_t)(q0 + row) * D_ + c4 * 4);
    }
    __syncthreads();
    wmma::fragment<wmma::matrix_a, 16, 16, 8, wmma::precision::tf32, wmma::row_major> Qf[8][2];
#pragma unroll
    for (int ks = 0; ks < 8; ks++)
#pragma unroll
        for (int i = 0; i < 2; i++)
            wmma::load_matrix_sync(Qf[ks][i], &Ps[(32 * wm + 16 * i) * 72 + ks * 8], 72);
    __syncthreads();

    float rs[8];
#pragma unroll
    for (int i = 0; i < 8; i++) rs[i] = 0.f;

    wmma::fragment<wmma::accumulator, 16, 16, 8, float> c_o[2][2];
#pragma unroll
    for (int i = 0; i < 2; i++)
#pragma unroll
        for (int j = 0; j < 2; j++) wmma::fill_fragment(c_o[i][j], 0.f);

    // prologue: chunk 0 (K/V 64x64, 512 thr -> 2 float4 each per matrix)
#pragma unroll
    for (int it = 0; it < 2; it++) {
        int row = prow + 32 * it;
        cpasync16(smem_u32 + (KB_OFF + row * 72 + pc4 * 4) * 4,
                  Kb + (size_t)row * D_ + pc4 * 4);
        cpasync16(smem_u32 + (VB_OFF + row * 72 + pc4 * 4) * 4,
                  Vb + (size_t)row * D_ + pc4 * 4);
    }
    cpasync_commit();

    for (int kc = 0; kc < 32; kc++) {
        const int cur = kc & 1;
        float* Kc = sm + KB_OFF + cur * KVSTRIDE;
        float* Vc = sm + VB_OFF + cur * KVSTRIDE;

        cpasync_wait0();
        __syncthreads();   // K/V ready; all warps done with Ps + old buffers

        if (kc + 1 < 32) {
            const int nxt = 1 - cur;
#pragma unroll
            for (int it = 0; it < 2; it++) {
                int row = prow + 32 * it;
                cpasync16(smem_u32 + (KB_OFF + nxt * KVSTRIDE + row * 72 + pc4 * 4) * 4,
                          Kb + (size_t)((kc + 1) * 64 + row) * D_ + pc4 * 4);
                cpasync16(smem_u32 + (VB_OFF + nxt * KVSTRIDE + row * 72 + pc4 * 4) * 4,
                          Vb + (size_t)((kc + 1) * 64 + row) * D_ + pc4 * 4);
            }
            cpasync_commit();
        }

        // ---- S = Q @ Kc^T : warp tile 32x32 over S tile 256x64 ----
        wmma::fragment<wmma::accumulator, 16, 16, 8, float> c_s[2][2];
#pragma unroll
        for (int i = 0; i < 2; i++)
#pragma unroll
            for (int j = 0; j < 2; j++) wmma::fill_fragment(c_s[i][j], 0.f);
#pragma unroll
        for (int ks = 0; ks < 8; ks++) {
            wmma::fragment<wmma::matrix_b, 16, 16, 8, wmma::precision::tf32, wmma::col_major> bb[2];
#pragma unroll
            for (int j = 0; j < 2; j++)
                wmma::load_matrix_sync(bb[j], &Kc[(32 * wn + 16 * j) * 72 + ks * 8], 72);
#pragma unroll
            for (int i = 0; i < 2; i++)
#pragma unroll
                for (int j = 0; j < 2; j++)
                    wmma::mma_sync(c_s[i][j], Qf[ks][i], bb[j], c_s[i][j]);
        }

        // ---- exp + tf32 round in fragments, single store to Ps ----
#pragma unroll
        for (int i = 0; i < 2; i++)
#pragma unroll
            for (int j = 0; j < 2; j++) {
#pragma unroll
                for (int e = 0; e < c_s[i][j].num_elements; e++)
                    c_s[i][j].x[e] = TF32(__expf(c_s[i][j].x[e] * 0.125f));
                wmma::store_matrix_sync(&Ps[(32 * wm + 16 * i) * 72 + 32 * wn + 16 * j],
                                        c_s[i][j], 72, wmma::mem_row_major);
            }
        __syncthreads();

        // ---- PV first: O += Ps(256x64) @ Vc(64x64) ----
#pragma unroll
        for (int ks = 0; ks < 8; ks++) {
            wmma::fragment<wmma::matrix_a, 16, 16, 8, wmma::precision::tf32, wmma::row_major> a2[2];
            wmma::fragment<wmma::matrix_b, 16, 16, 8, wmma::precision::tf32, wmma::row_major> b2[2];
#pragma unroll
            for (int i = 0; i < 2; i++)
                wmma::load_matrix_sync(a2[i], &Ps[(32 * wm + 16 * i) * 72 + ks * 8], 72);
#pragma unroll
            for (int j = 0; j < 2; j++)
                wmma::load_matrix_sync(b2[j], &Vc[(ks * 8) * 72 + 32 * wn + 16 * j], 72);
#pragma unroll
            for (int i = 0; i < 2; i++)
#pragma unroll
                for (int j = 0; j < 2; j++)
                    wmma::mma_sync(c_o[i][j], a2[i], b2[j], c_o[i][j]);
        }

        // ---- then rowsums + gmem P write (overlaps tensor drain) ----
#pragma unroll
        for (int it = 0; it < 8; it++) {
            int row = prow + 32 * it;
            float4 v = *(float4*)&Ps[row * 72 + pc4 * 4];
            float s = v.x + v.y + v.z + v.w;
            s += __shfl_xor_sync(0xffffffffu, s, 1);
            s += __shfl_xor_sync(0xffffffffu, s, 2);
            s += __shfl_xor_sync(0xffffffffu, s, 4);
            s += __shfl_xor_sync(0xffffffffu, s, 8);
            rs[it] += s;
            *(float4*)(Pb + (size_t)(q0 + row) * S_ + kc * 64 + pc4 * 4) = v;
        }
    }

    // ---- thread-local rescale of the P words this thread wrote ----
#pragma unroll
    for (int it = 0; it < 8; it++) {
        const int row = prow + 32 * it;
        const float inv = 1.0f / rs[it];
        float* base = Pb + (size_t)(q0 + row) * S_ + pc4 * 4;
#pragma unroll 8
        for (int kc = 0; kc < 32; kc++) {
            float4 v = *(float4*)(base + kc * 64);
            v.x *= inv; v.y *= inv; v.z *= inv; v.w *= inv;
            *(float4*)(base + kc * 64) = v;
        }
    }

    __syncthreads();   // all warps done with Ps (last PV reads)

    // ---- O staging + AO write ----
#pragma unroll
    for (int i = 0; i < 2; i++)
#pragma unroll
        for (int j = 0; j < 2; j++)
            wmma::store_matrix_sync(&Ps[(32 * wm + 16 * i) * 72 + 32 * wn + 16 * j],
                                    c_o[i][j], 72, wmma::mem_row_major);
    __syncthreads();

#pragma unroll
    for (int it = 0; it < 8; it++) {
        int row = prow + 32 * it;
        const float inv = 1.0f / rs[it];
        float4 v = *(float4*)&Ps[row * 72 + pc4 * 4];
        v.x = TF32(v.x * inv); v.y = TF32(v.y * inv);
        v.z = TF32(v.z * inv); v.w = TF32(v.w * inv);
        *(float4*)(AO + ((size_t)b * S_ + q0 + row) * D_ + h * DK_ + pc4 * 4) = v;
    }
}

// ---------------------------------------------------------------------------
extern "C" void kernel_launch(void* const* d_in, const int* in_sizes, int n_in,
                              void* d_out, int out_size)
{
    const float* query = (const float*)d_in[0];
    const float* key_  = (const float*)d_in[1];
    const float* value = (const float*)d_in[2];
    const float* Wq = (const float*)d_in[3];
    const float* bq = (const float*)d_in[4];
    const float* Wk = (const float*)d_in[5];
    const float* bk = (const float*)d_in[6];
    const float* Wv = (const float*)d_in[7];
    const float* bv = (const float*)d_in[8];
    const float* Wo = (const float*)d_in[9];
    const float* bo = (const float*)d_in[10];

    float* out  = (float*)d_out;
    float* attn = out + (size_t)B_ * S_ * D_;

    float *Qp, *Kp, *Vp, *AOp;
    cudaGetSymbolAddress((void**)&Qp,  g_Q);
    cudaGetSymbolAddress((void**)&Kp,  g_K);
    cudaGetSymbolAddress((void**)&Vp,  g_V);
    cudaGetSymbolAddress((void**)&AOp, g_AO);

    cudaFuncSetAttribute(fused_attn,
                         cudaFuncAttributeMaxDynamicSharedMemorySize,
                         FA_SMEM_BYTES);

    qkv_proj<<<dim3(8, 64, 3), 256>>>(query, key_, value,
                                      Wq, bq, Wk, bk, Wv, bv,
                                      Qp, Kp, Vp);

    fused_attn<<<dim3(S_ / QR, 64), 512, FA_SMEM_BYTES>>>(Qp, Kp, Vp, attn, AOp);

    out_proj<<<dim3(8, 64), 256>>>(AOp, Wo, bo, out);
}

// round 11
// speedup vs baseline: 2.7546x; 2.7546x over previous
#include <cuda_runtime.h>
#include <mma.h>
#include <cuda_fp16.h>
#include <cstdint>

using namespace nvcuda;

#define B_  4
#define S_  2048
#define D_  1024
#define H_  16
#define DK_ 64

// Scratch (__device__ globals; no allocs allowed).
__device__ __half g_Qh[(size_t)B_*S_*D_];   // holds Qproj * 0.125
__device__ __half g_Kh[(size_t)B_*S_*D_];
__device__ __half g_Vh[(size_t)B_*S_*D_];
__device__ float  g_AO[(size_t)B_*S_*D_];

__device__ __forceinline__ void cpasync16(uint32_t saddr, const void* g) {
    asm volatile("cp.async.cg.shared.global [%0], [%1], 16;" :: "r"(saddr), "l"(g));
}
__device__ __forceinline__ void cpasync_commit() {
    asm volatile("cp.async.commit_group;");
}
__device__ __forceinline__ void cpasync_wait0() {
    asm volatile("cp.async.wait_group 0;");
}

// ---------------------------------------------------------------------------
// fp16 NT GEMM body: C = A @ W^T + bias.  A [M,1024] fp32, W [N,1024] fp32,
// both K-contiguous. BM=BN=128, BK=32, 256 thr, 8 warps (2x4), warp 64x32.
// m16n16k16 wmma, fp32 accumulate. Inputs rounded to half at smem store.
// mode 0: fp32 out.  mode 1: half out.  mode 2: half out * 0.125.
// ---------------------------------------------------------------------------
#define LDH 40   // halves per smem row (80B: 8-row LDSM phases conflict-free)

__device__ __forceinline__ void gemm16_body(
    const float* __restrict__ A, const float* __restrict__ W,
    const float* __restrict__ bias, float* __restrict__ Cf,
    __half* __restrict__ Ch, int mode,
    __half* Ah, __half* Bh, float* Cs)
{
    const int tid = threadIdx.x;
    const int w = tid >> 5, lane = tid & 31;
    const int wm = w >> 2, wn = w & 3;
    const size_t m0 = (size_t)blockIdx.y * 128;
    const size_t n0 = (size_t)blockIdx.x * 128;

    wmma::fragment<wmma::accumulator, 16, 16, 16, float> c[4][2];
#pragma unroll
    for (int i = 0; i < 4; i++)
#pragma unroll
        for (int j = 0; j < 2; j++) wmma::fill_fragment(c[i][j], 0.f);

    for (int k0 = 0; k0 < 1024; k0 += 32) {
        float4 av[4], bv[4];
#pragma unroll
        for (int it = 0; it < 4; it++) {
            int idx = tid + 256 * it;
            int row = idx >> 3, c4 = idx & 7;      // 128 rows x 8 float4
            av[it] = *(const float4*)(A + (m0 + row) * 1024 + k0 + c4 * 4);
            bv[it] = *(const float4*)(W + (n0 + row) * 1024 + k0 + c4 * 4);
        }
        __syncthreads();
#pragma unroll
        for (int it = 0; it < 4; it++) {
            int idx = tid + 256 * it;
            int row = idx >> 3, c4 = idx & 7;
            half2 a0 = __floats2half2_rn(av[it].x, av[it].y);
            half2 a1 = __floats2half2_rn(av[it].z, av[it].w);
            half2 b0 = __floats2half2_rn(bv[it].x, bv[it].y);
            half2 b1 = __floats2half2_rn(bv[it].z, bv[it].w);
            *(half2*)&Ah[row * LDH + c4 * 4]     = a0;
            *(half2*)&Ah[row * LDH + c4 * 4 + 2] = a1;
            *(half2*)&Bh[row * LDH + c4 * 4]     = b0;
            *(half2*)&Bh[row * LDH + c4 * 4 + 2] = b1;
        }
        __syncthreads();

#pragma unroll
        for (int ks = 0; ks < 2; ks++) {
            wmma::fragment<wmma::matrix_a, 16, 16, 16, __half, wmma::row_major> a[4];
            wmma::fragment<wmma::matrix_b, 16, 16, 16, __half, wmma::col_major> b[2];
#pragma unroll
            for (int i = 0; i < 4; i++)
                wmma::load_matrix_sync(a[i], &Ah[(64 * wm + 16 * i) * LDH + ks * 16], LDH);
#pragma unroll
            for (int j = 0; j < 2; j++)
                wmma::load_matrix_sync(b[j], &Bh[(32 * wn + 16 * j) * LDH + ks * 16], LDH);
#pragma unroll
            for (int i = 0; i < 4; i++)
#pragma unroll
                for (int j = 0; j < 2; j++)
                    wmma::mma_sync(c[i][j], a[i], b[j], c[i][j]);
        }
        __syncthreads();
    }

    float* buf = Cs + w * 320;
#pragma unroll
    for (int i = 0; i < 4; i++) {
#pragma unroll
        for (int j = 0; j < 2; j++) {
            wmma::store_matrix_sync(buf, c[i][j], 20, wmma::mem_row_major);
            __syncwarp();
            const int rr = lane >> 1, ch = (lane & 1) * 8;
            const size_t gr = m0 + 64 * wm + 16 * i + rr;
            const size_t gc = n0 + 32 * wn + 16 * j + ch;
            float4 v0 = *(float4*)&buf[rr * 20 + ch];
            float4 v1 = *(float4*)&buf[rr * 20 + ch + 4];
            v0.x += bias[gc + 0]; v0.y += bias[gc + 1];
            v0.z += bias[gc + 2]; v0.w += bias[gc + 3];
            v1.x += bias[gc + 4]; v1.y += bias[gc + 5];
            v1.z += bias[gc + 6]; v1.w += bias[gc + 7];
            if (mode == 0) {
                *(float4*)(Cf + gr * 1024 + gc)     = v0;
                *(float4*)(Cf + gr * 1024 + gc + 4) = v1;
            } else {
                if (mode == 2) {
                    v0.x *= 0.125f; v0.y *= 0.125f; v0.z *= 0.125f; v0.w *= 0.125f;
                    v1.x *= 0.125f; v1.y *= 0.125f; v1.z *= 0.125f; v1.w *= 0.125f;
                }
                half2 h0 = __floats2half2_rn(v0.x, v0.y);
                half2 h1 = __floats2half2_rn(v0.z, v0.w);
                half2 h2 = __floats2half2_rn(v1.x, v1.y);
                half2 h3 = __floats2half2_rn(v1.z, v1.w);
                uint4 pk;
                pk.x = *(uint32_t*)&h0; pk.y = *(uint32_t*)&h1;
                pk.z = *(uint32_t*)&h2; pk.w = *(uint32_t*)&h3;
                *(uint4*)(Ch + gr * 1024 + gc) = pk;
            }
            __syncwarp();
        }
    }
}

#define G16_SMEM_HALVES (128 * LDH)

__global__ __launch_bounds__(256) void qkv16(
    const float* __restrict__ q,  const float* __restrict__ k,
    const float* __restrict__ v,
    const float* __restrict__ wq, const float* __restrict__ bq,
    const float* __restrict__ wk, const float* __restrict__ bk,
    const float* __restrict__ wv, const float* __restrict__ bv,
    __half* __restrict__ Qo, __half* __restrict__ Ko, __half* __restrict__ Vo)
{
    __shared__ __half Ah[G16_SMEM_HALVES];
    __shared__ __half Bh[G16_SMEM_HALVES];
    __shared__ float  Cs[8 * 320];
    const float *A, *W, *bi; __half* C; int mode;
    if (blockIdx.z == 0)      { A = q; W = wq; bi = bq; C = Qo; mode = 2; }
    else if (blockIdx.z == 1) { A = k; W = wk; bi = bk; C = Ko; mode = 1; }
    else                      { A = v; W = wv; bi = bv; C = Vo; mode = 1; }
    gemm16_body(A, W, bi, nullptr, C, mode, Ah, Bh, Cs);
}

__global__ __launch_bounds__(256) void out16(
    const float* __restrict__ A, const float* __restrict__ W,
    const float* __restrict__ bi, float* __restrict__ C)
{
    __shared__ __half Ah[G16_SMEM_HALVES];
    __shared__ __half Bh[G16_SMEM_HALVES];
    __shared__ float  Cs[8 * 320];
    gemm16_body(A, W, bi, C, nullptr, 0, Ah, Bh, Cs);
}

// ---------------------------------------------------------------------------
// Fused attention (fp16 MMA): q-tile 128, 256 thr, 2 CTAs/SM.
// Q prescaled by 1/8 -> S accum, exp(S) in frags -> fp32 stage -> rowsum +
// fp32 gmem P + half PsH -> fp16 PV. Tail: thread-local P rescale, AO fp32.
// Smem bytes: Sst f32 128*72 @0 (36864), PsH half 128*72 @36864 (18432),
//             KB dbl @55296 (18432), VB dbl @73728 (18432). total 92160.
// ---------------------------------------------------------------------------
#define FA_SMEM_BYTES 92160
#define KB_BOFF 55296
#define VB_BOFF 73728
#define KV_BSTRIDE 9216

__global__ __launch_bounds__(256, 2) void fused_attn16(
    const __half* __restrict__ Q, const __half* __restrict__ K,
    const __half* __restrict__ V, float* __restrict__ P,
    float* __restrict__ AO)
{
    extern __shared__ char smc[];
    float*  Sst = (float*)smc;
    __half* PsH = (__half*)(smc + 36864);
    const uint32_t smb = (uint32_t)__cvta_generic_to_shared(smc);

    const int tid = threadIdx.x, w = tid >> 5;
    const int wm = w >> 1, wn = w & 1;          // 4x2 warp grid, 32x32 tiles
    const int bh = blockIdx.y, b = bh >> 4, h = bh & 15;
    const int q0 = blockIdx.x * 128;
    const int prow = tid >> 4, pc4 = tid & 15;  // f32 pass mapping
    const int crow = tid >> 3, cc = tid & 7;    // K/V copy: 64rows x 8 chunks

    const __half* Qb = Q + (size_t)b * S_ * D_ + h * DK_;
    const __half* Kb = K + (size_t)b * S_ * D_ + h * DK_;
    const __half* Vb = V + (size_t)b * S_ * D_ + h * DK_;
    float* Pb = P + (size_t)bh * S_ * S_;

    // ---- Stage Q tile [128x64 half] into PsH, preload fragments ----
#pragma unroll
    for (int it = 0; it < 4; it++) {
        int idx = tid + 256 * it;               // 0..1023
        int row = idx >> 3, c = idx & 7;
        *(uint4*)&PsH[row * 72 + c * 8] =
            *(const uint4*)(Qb + (size_t)(q0 + row) * D_ + c * 8);
    }
    __syncthreads();
    wmma::fragment<wmma::matrix_a, 16, 16, 16, __half, wmma::row_major> Qf[4][2];
#pragma unroll
    for (int ks = 0; ks < 4; ks++)
#pragma unroll
        for (int i = 0; i < 2; i++)
            wmma::load_matrix_sync(Qf[ks][i], &PsH[(32 * wm + 16 * i) * 72 + ks * 16], 72);
    __syncthreads();

    float rs[8];
#pragma unroll
    for (int i = 0; i < 8; i++) rs[i] = 0.f;

    wmma::fragment<wmma::accumulator, 16, 16, 16, float> c_o[2][2];
#pragma unroll
    for (int i = 0; i < 2; i++)
#pragma unroll
        for (int j = 0; j < 2; j++) wmma::fill_fragment(c_o[i][j], 0.f);

    // prologue: chunk 0 (64 rows x 128B per matrix, 2 chunks/thread each)
#pragma unroll
    for (int it = 0; it < 2; it++) {
        int row = crow + 32 * it;
        cpasync16(smb + KB_BOFF + row * 144 + cc * 16,
                  Kb + (size_t)row * D_ + cc * 8);
        cpasync16(smb + VB_BOFF + row * 144 + cc * 16,
                  Vb + (size_t)row * D_ + cc * 8);
    }
    cpasync_commit();

    for (int kc = 0; kc < 32; kc++) {
        const int cur = kc & 1;
        __half* Kc = (__half*)(smc + KB_BOFF + cur * KV_BSTRIDE);
        __half* Vc = (__half*)(smc + VB_BOFF + cur * KV_BSTRIDE);

        cpasync_wait0();
        __syncthreads();

        if (kc + 1 < 32) {
            const int nxt = 1 - cur;
#pragma unroll
            for (int it = 0; it < 2; it++) {
                int row = crow + 32 * it;
                cpasync16(smb + KB_BOFF + nxt * KV_BSTRIDE + row * 144 + cc * 16,
                          Kb + (size_t)((kc + 1) * 64 + row) * D_ + cc * 8);
                cpasync16(smb + VB_BOFF + nxt * KV_BSTRIDE + row * 144 + cc * 16,
                          Vb + (size_t)((kc + 1) * 64 + row) * D_ + cc * 8);
            }
            cpasync_commit();
        }

        // ---- S = (Q/8) @ Kc^T : 4 k16 steps ----
        wmma::fragment<wmma::accumulator, 16, 16, 16, float> c_s[2][2];
#pragma unroll
        for (int i = 0; i < 2; i++)
#pragma unroll
            for (int j = 0; j < 2; j++) wmma::fill_fragment(c_s[i][j], 0.f);
#pragma unroll
        for (int ks = 0; ks < 4; ks++) {
            wmma::fragment<wmma::matrix_b, 16, 16, 16, __half, wmma::col_major> bb[2];
#pragma unroll
            for (int j = 0; j < 2; j++)
                wmma::load_matrix_sync(bb[j], &Kc[(32 * wn + 16 * j) * 72 + ks * 16], 72);
#pragma unroll
            for (int i = 0; i < 2; i++)
#pragma unroll
                for (int j = 0; j < 2; j++)
                    wmma::mma_sync(c_s[i][j], Qf[ks][i], bb[j], c_s[i][j]);
        }

        // ---- exp in fragments, store fp32 stage ----
#pragma unroll
        for (int i = 0; i < 2; i++)
#pragma unroll
            for (int j = 0; j < 2; j++) {
#pragma unroll
                for (int e = 0; e < c_s[i][j].num_elements; e++)
                    c_s[i][j].x[e] = __expf(c_s[i][j].x[e]);
                wmma::store_matrix_sync(&Sst[(32 * wm + 16 * i) * 72 + 32 * wn + 16 * j],
                                        c_s[i][j], 72, wmma::mem_row_major);
            }
        __syncthreads();

        // ---- pass: rowsums + fp32 gmem P + half PsH ----
#pragma unroll
        for (int it = 0; it < 8; it++) {
            int row = prow + 16 * it;
            float4 v = *(float4*)&Sst[row * 72 + pc4 * 4];
            float s = v.x + v.y + v.z + v.w;
            s += __shfl_xor_sync(0xffffffffu, s, 1);
            s += __shfl_xor_sync(0xffffffffu, s, 2);
            s += __shfl_xor_sync(0xffffffffu, s, 4);
            s += __shfl_xor_sync(0xffffffffu, s, 8);
            rs[it] += s;
            *(float4*)(Pb + (size_t)(q0 + row) * S_ + kc * 64 + pc4 * 4) = v;
            half2 h0 = __floats2half2_rn(v.x, v.y);
            half2 h1 = __floats2half2_rn(v.z, v.w);
            uint2 pk; pk.x = *(uint32_t*)&h0; pk.y = *(uint32_t*)&h1;
            *(uint2*)&PsH[row * 72 + pc4 * 4] = pk;
        }
        __syncthreads();

        // ---- O += PsH(128x64) @ Vc(64x64) : 4 k16 steps ----
#pragma unroll
        for (int ks = 0; ks < 4; ks++) {
            wmma::fragment<wmma::matrix_a, 16, 16, 16, __half, wmma::row_major> a2[2];
            wmma::fragment<wmma::matrix_b, 16, 16, 16, __half, wmma::row_major> b2[2];
#pragma unroll
            for (int i = 0; i < 2; i++)
                wmma::load_matrix_sync(a2[i], &PsH[(32 * wm + 16 * i) * 72 + ks * 16], 72);
#pragma unroll
            for (int j = 0; j < 2; j++)
                wmma::load_matrix_sync(b2[j], &Vc[(ks * 16) * 72 + 32 * wn + 16 * j], 72);
#pragma unroll
            for (int i = 0; i < 2; i++)
#pragma unroll
                for (int j = 0; j < 2; j++)
                    wmma::mma_sync(c_o[i][j], a2[i], b2[j], c_o[i][j]);
        }
    }

    // ---- thread-local rescale of the P words this thread wrote ----
#pragma unroll
    for (int it = 0; it < 8; it++) {
        const int row = prow + 16 * it;
        const float inv = 1.0f / rs[it];
        float* base = Pb + (size_t)(q0 + row) * S_ + pc4 * 4;
#pragma unroll 8
        for (int kc = 0; kc < 32; kc++) {
            float4 v = *(float4*)(base + kc * 64);
            v.x *= inv; v.y *= inv; v.z *= inv; v.w *= inv;
            *(float4*)(base + kc * 64) = v;
        }
    }

    // ---- O frags -> fp32 stage -> AO (fp32, normalized) ----
#pragma unroll
    for (int i = 0; i < 2; i++)
#pragma unroll
        for (int j = 0; j < 2; j++)
            wmma::store_matrix_sync(&Sst[(32 * wm + 16 * i) * 72 + 32 * wn + 16 * j],
                                    c_o[i][j], 72, wmma::mem_row_major);
    __syncthreads();

#pragma unroll
    for (int it = 0; it < 8; it++) {
        int row = prow + 16 * it;
        const float inv = 1.0f / rs[it];
        float4 v = *(float4*)&Sst[row * 72 + pc4 * 4];
        v.x *= inv; v.y *= inv; v.z *= inv; v.w *= inv;
        *(float4*)(AO + ((size_t)b * S_ + q0 + row) * D_ + h * DK_ + pc4 * 4) = v;
    }
}

// ---------------------------------------------------------------------------
extern "C" void kernel_launch(void* const* d_in, const int* in_sizes, int n_in,
                              void* d_out, int out_size)
{
    const float* query = (const float*)d_in[0];
    const float* key_  = (const float*)d_in[1];
    const float* value = (const float*)d_in[2];
    const float* Wq = (const float*)d_in[3];
    const float* bq = (const float*)d_in[4];
    const float* Wk = (const float*)d_in[5];
    const float* bk = (const float*)d_in[6];
    const float* Wv = (const float*)d_in[7];
    const float* bv = (const float*)d_in[8];
    const float* Wo = (const float*)d_in[9];
    const float* bo = (const float*)d_in[10];

    float* out  = (float*)d_out;
    float* attn = out + (size_t)B_ * S_ * D_;

    __half *Qh, *Kh, *Vh; float *AOp;
    cudaGetSymbolAddress((void**)&Qh,  g_Qh);
    cudaGetSymbolAddress((void**)&Kh,  g_Kh);
    cudaGetSymbolAddress((void**)&Vh,  g_Vh);
    cudaGetSymbolAddress((void**)&AOp, g_AO);

    cudaFuncSetAttribute(fused_attn16,
                         cudaFuncAttributeMaxDynamicSharedMemorySize, FA_SMEM_BYTES);

    qkv16<<<dim3(8, 64, 3), 256>>>(query, key_, value,
                                   Wq, bq, Wk, bk, Wv, bv,
                                   Qh, Kh, Vh);

    fused_attn16<<<dim3(16, 64), 256, FA_SMEM_BYTES>>>(Qh, Kh, Vh, attn, AOp);

    out16<<<dim3(8, 64), 256>>>(AOp, Wo, bo, out);
}

// round 12
// speedup vs baseline: 3.0414x; 1.1041x over previous
#include <cuda_runtime.h>
#include <mma.h>
#include <cuda_fp16.h>
#include <cstdint>

using namespace nvcuda;

#define B_  4
#define S_  2048
#define D_  1024
#define H_  16
#define DK_ 64

// Scratch (__device__ globals; no allocs allowed).
__device__ __half g_Xq[(size_t)B_*S_*D_];
__device__ __half g_Xk[(size_t)B_*S_*D_];
__device__ __half g_Xv[(size_t)B_*S_*D_];
__device__ __half g_Wh[4][(size_t)D_*D_];
__device__ __half g_Qh[(size_t)B_*S_*D_];   // Qproj * 0.125
__device__ __half g_Kh[(size_t)B_*S_*D_];
__device__ __half g_Vh[(size_t)B_*S_*D_];
__device__ __half g_AOh[(size_t)B_*S_*D_];

__device__ __forceinline__ void cpasync16(uint32_t saddr, const void* g) {
    asm volatile("cp.async.cg.shared.global [%0], [%1], 16;" :: "r"(saddr), "l"(g));
}
__device__ __forceinline__ void cpasync_commit() {
    asm volatile("cp.async.commit_group;");
}
__device__ __forceinline__ void cpasync_wait0() {
    asm volatile("cp.async.wait_group 0;");
}

// ---------------------------------------------------------------------------
// fp32 -> fp16 conversion pass.
// ---------------------------------------------------------------------------
__global__ __launch_bounds__(256) void tohalf(const float* __restrict__ in,
                                              __half* __restrict__ outp, int n4)
{
    int i = blockIdx.x * 256 + threadIdx.x;
    int stride = gridDim.x * 256;
    for (; i < n4; i += stride) {
        float4 v = ((const float4*)in)[i];
        half2 h0 = __floats2half2_rn(v.x, v.y);
        half2 h1 = __floats2half2_rn(v.z, v.w);
        uint2 pk; pk.x = *(uint32_t*)&h0; pk.y = *(uint32_t*)&h1;
        ((uint2*)outp)[i] = pk;
    }
}

// ---------------------------------------------------------------------------
// fp16 NT GEMM (pre-converted inputs): C = A @ W^T + bias.
// A [M,1024] half, W [N,1024] half, K-contiguous. BM=BN=128, BK=64,
// cp.async double-buffered, 1 barrier/slab. 256 thr, warp tile 64x32.
// mode 0: fp32 out. 1: half out. 2: half out * 0.125.
// Dyn smem bytes: Abuf 2x18432 @0, Bbuf 2x18432 @36864, Cs f32 @73728(10240).
// ---------------------------------------------------------------------------
#define GB_BUF 18432
#define G16_SMEM_BYTES 83968

__device__ __forceinline__ void gemm16_body(
    const __half* __restrict__ A, const __half* __restrict__ W,
    const float* __restrict__ bias, float* __restrict__ Cf,
    __half* __restrict__ Ch, int mode, char* smc)
{
    const int tid = threadIdx.x;
    const int w = tid >> 5, lane = tid & 31;
    const int wm = w >> 2, wn = w & 3;
    const size_t m0 = (size_t)blockIdx.y * 128;
    const size_t n0 = (size_t)blockIdx.x * 128;
    const uint32_t smb = (uint32_t)__cvta_generic_to_shared(smc);
    const int crow = tid >> 1;                 // 128 rows, 2 thr/row
    const int cc0  = (tid & 1) * 4;            // 4 chunks of 16B each

    wmma::fragment<wmma::accumulator, 16, 16, 16, float> c[4][2];
#pragma unroll
    for (int i = 0; i < 4; i++)
#pragma unroll
        for (int j = 0; j < 2; j++) wmma::fill_fragment(c[i][j], 0.f);

    // prologue: slab 0
#pragma unroll
    for (int ch = 0; ch < 4; ch++) {
        cpasync16(smb + crow * 144 + (cc0 + ch) * 16,
                  A + (m0 + crow) * 1024 + (cc0 + ch) * 8);
        cpasync16(smb + 36864 + crow * 144 + (cc0 + ch) * 16,
                  W + (n0 + crow) * 1024 + (cc0 + ch) * 8);
    }
    cpasync_commit();

    for (int kb = 0; kb < 16; kb++) {
        const int cur = kb & 1;
        cpasync_wait0();
        __syncthreads();

        if (kb < 15) {
            const int nxt = 1 - cur;
            const int k0 = (kb + 1) * 64;
#pragma unroll
            for (int ch = 0; ch < 4; ch++) {
                cpasync16(smb + nxt * GB_BUF + crow * 144 + (cc0 + ch) * 16,
                          A + (m0 + crow) * 1024 + k0 + (cc0 + ch) * 8);
                cpasync16(smb + 36864 + nxt * GB_BUF + crow * 144 + (cc0 + ch) * 16,
                          W + (n0 + crow) * 1024 + k0 + (cc0 + ch) * 8);
            }
            cpasync_commit();
        }

        const __half* ah = (const __half*)(smc + cur * GB_BUF);
        const __half* bh = (const __half*)(smc + 36864 + cur * GB_BUF);
#pragma unroll
        for (int ks = 0; ks < 4; ks++) {
            wmma::fragment<wmma::matrix_a, 16, 16, 16, __half, wmma::row_major> a[4];
            wmma::fragment<wmma::matrix_b, 16, 16, 16, __half, wmma::col_major> b[2];
#pragma unroll
            for (int i = 0; i < 4; i++)
                wmma::load_matrix_sync(a[i], &ah[(64 * wm + 16 * i) * 72 + ks * 16], 72);
#pragma unroll
            for (int j = 0; j < 2; j++)
                wmma::load_matrix_sync(b[j], &bh[(32 * wn + 16 * j) * 72 + ks * 16], 72);
#pragma unroll
            for (int i = 0; i < 4; i++)
#pragma unroll
                for (int j = 0; j < 2; j++)
                    wmma::mma_sync(c[i][j], a[i], b[j], c[i][j]);
        }
    }

    float* buf = (float*)(smc + 73728) + w * 320;
#pragma unroll
    for (int i = 0; i < 4; i++) {
#pragma unroll
        for (int j = 0; j < 2; j++) {
            wmma::store_matrix_sync(buf, c[i][j], 20, wmma::mem_row_major);
            __syncwarp();
            const int rr = lane >> 1, ch = (lane & 1) * 8;
            const size_t gr = m0 + 64 * wm + 16 * i + rr;
            const size_t gc = n0 + 32 * wn + 16 * j + ch;
            float4 v0 = *(float4*)&buf[rr * 20 + ch];
            float4 v1 = *(float4*)&buf[rr * 20 + ch + 4];
            v0.x += bias[gc + 0]; v0.y += bias[gc + 1];
            v0.z += bias[gc + 2]; v0.w += bias[gc + 3];
            v1.x += bias[gc + 4]; v1.y += bias[gc + 5];
            v1.z += bias[gc + 6]; v1.w += bias[gc + 7];
            if (mode == 0) {
                *(float4*)(Cf + gr * 1024 + gc)     = v0;
                *(float4*)(Cf + gr * 1024 + gc + 4) = v1;
            } else {
                if (mode == 2) {
                    v0.x *= 0.125f; v0.y *= 0.125f; v0.z *= 0.125f; v0.w *= 0.125f;
                    v1.x *= 0.125f; v1.y *= 0.125f; v1.z *= 0.125f; v1.w *= 0.125f;
                }
                half2 h0 = __floats2half2_rn(v0.x, v0.y);
                half2 h1 = __floats2half2_rn(v0.z, v0.w);
                half2 h2 = __floats2half2_rn(v1.x, v1.y);
                half2 h3 = __floats2half2_rn(v1.z, v1.w);
                uint4 pk;
                pk.x = *(uint32_t*)&h0; pk.y = *(uint32_t*)&h1;
                pk.z = *(uint32_t*)&h2; pk.w = *(uint32_t*)&h3;
                *(uint4*)(Ch + gr * 1024 + gc) = pk;
            }
            __syncwarp();
        }
    }
}

__global__ __launch_bounds__(256) void qkv16(
    const __half* __restrict__ xq, const __half* __restrict__ xk,
    const __half* __restrict__ xv,
    const __half* __restrict__ wq, const float* __restrict__ bq,
    const __half* __restrict__ wk, const float* __restrict__ bk,
    const __half* __restrict__ wv, const float* __restrict__ bv,
    __half* __restrict__ Qo, __half* __restrict__ Ko, __half* __restrict__ Vo)
{
    extern __shared__ char smc[];
    const __half *A, *W; const float* bi; __half* C; int mode;
    if (blockIdx.z == 0)      { A = xq; W = wq; bi = bq; C = Qo; mode = 2; }
    else if (blockIdx.z == 1) { A = xk; W = wk; bi = bk; C = Ko; mode = 1; }
    else                      { A = xv; W = wv; bi = bv; C = Vo; mode = 1; }
    gemm16_body(A, W, bi, nullptr, C, mode, smc);
}

__global__ __launch_bounds__(256) void out16(
    const __half* __restrict__ A, const __half* __restrict__ W,
    const float* __restrict__ bi, float* __restrict__ C)
{
    extern __shared__ char smc[];
    gemm16_body(A, W, bi, C, nullptr, 0, smc);
}

// ---------------------------------------------------------------------------
// Fused attention, TWO-PASS (single normalized P write):
// pass 1: rowsums only (S mma + exp + reduce; K loads only).
// pass 2: S mma + exp, scale by inv in staging pass, write fp32 P once,
//         fp16 PV with normalized PsH -> O normalized; AO written as half.
// Smem: Sst f32 128*72 @0 (36864), PsH half @36864 (18432),
//       KB dbl @55296 (18432), VB dbl @73728 (18432). total 92160 B.
// ---------------------------------------------------------------------------
#define FA_SMEM_BYTES 92160
#define KB_BOFF 55296
#define VB_BOFF 73728
#define KV_BSTRIDE 9216

__global__ __launch_bounds__(256, 2) void fused_attn16(
    const __half* __restrict__ Q, const __half* __restrict__ K,
    const __half* __restrict__ V, float* __restrict__ P,
    __half* __restrict__ AO)
{
    extern __shared__ char smc[];
    float*  Sst = (float*)smc;
    __half* PsH = (__half*)(smc + 36864);
    const uint32_t smb = (uint32_t)__cvta_generic_to_shared(smc);

    const int tid = threadIdx.x, w = tid >> 5;
    const int wm = w >> 1, wn = w & 1;          // 4x2 warp grid, 32x32 tiles
    const int bh = blockIdx.y, b = bh >> 4, h = bh & 15;
    const int q0 = blockIdx.x * 128;
    const int prow = tid >> 4, pc4 = tid & 15;  // staging-pass mapping
    const int crow = tid >> 3, cc = tid & 7;    // K/V copy mapping

    const __half* Qb = Q + (size_t)b * S_ * D_ + h * DK_;
    const __half* Kb = K + (size_t)b * S_ * D_ + h * DK_;
    const __half* Vb = V + (size_t)b * S_ * D_ + h * DK_;
    float* Pb = P + (size_t)bh * S_ * S_;

    // ---- Stage Q tile [128x64 half] into PsH, preload fragments ----
#pragma unroll
    for (int it = 0; it < 4; it++) {
        int idx = tid + 256 * it;
        int row = idx >> 3, c = idx & 7;
        *(uint4*)&PsH[row * 72 + c * 8] =
            *(const uint4*)(Qb + (size_t)(q0 + row) * D_ + c * 8);
    }
    __syncthreads();
    wmma::fragment<wmma::matrix_a, 16, 16, 16, __half, wmma::row_major> Qf[4][2];
#pragma unroll
    for (int ks = 0; ks < 4; ks++)
#pragma unroll
        for (int i = 0; i < 2; i++)
            wmma::load_matrix_sync(Qf[ks][i], &PsH[(32 * wm + 16 * i) * 72 + ks * 16], 72);
    __syncthreads();

    float rs[8];
#pragma unroll
    for (int i = 0; i < 8; i++) rs[i] = 0.f;

    // ================= PASS 1: rowsums =================
#pragma unroll
    for (int it = 0; it < 2; it++) {
        int row = crow + 32 * it;
        cpasync16(smb + KB_BOFF + row * 144 + cc * 16,
                  Kb + (size_t)row * D_ + cc * 8);
    }
    cpasync_commit();

    for (int kc = 0; kc < 32; kc++) {
        const int cur = kc & 1;
        __half* Kc = (__half*)(smc + KB_BOFF + cur * KV_BSTRIDE);

        cpasync_wait0();
        __syncthreads();

        if (kc + 1 < 32) {
            const int nxt = 1 - cur;
#pragma unroll
            for (int it = 0; it < 2; it++) {
                int row = crow + 32 * it;
                cpasync16(smb + KB_BOFF + nxt * KV_BSTRIDE + row * 144 + cc * 16,
                          Kb + (size_t)((kc + 1) * 64 + row) * D_ + cc * 8);
            }
            cpasync_commit();
        }

        wmma::fragment<wmma::accumulator, 16, 16, 16, float> c_s[2][2];
#pragma unroll
        for (int i = 0; i < 2; i++)
#pragma unroll
            for (int j = 0; j < 2; j++) wmma::fill_fragment(c_s[i][j], 0.f);
#pragma unroll
        for (int ks = 0; ks < 4; ks++) {
            wmma::fragment<wmma::matrix_b, 16, 16, 16, __half, wmma::col_major> bb[2];
#pragma unroll
            for (int j = 0; j < 2; j++)
                wmma::load_matrix_sync(bb[j], &Kc[(32 * wn + 16 * j) * 72 + ks * 16], 72);
#pragma unroll
            for (int i = 0; i < 2; i++)
#pragma unroll
                for (int j = 0; j < 2; j++)
                    wmma::mma_sync(c_s[i][j], Qf[ks][i], bb[j], c_s[i][j]);
        }

#pragma unroll
        for (int i = 0; i < 2; i++)
#pragma unroll
            for (int j = 0; j < 2; j++) {
#pragma unroll
                for (int e = 0; e < c_s[i][j].num_elements; e++)
                    c_s[i][j].x[e] = __expf(c_s[i][j].x[e]);
                wmma::store_matrix_sync(&Sst[(32 * wm + 16 * i) * 72 + 32 * wn + 16 * j],
                                        c_s[i][j], 72, wmma::mem_row_major);
            }
        __syncthreads();

#pragma unroll
        for (int it = 0; it < 8; it++) {
            int row = prow + 16 * it;
            float4 v = *(float4*)&Sst[row * 72 + pc4 * 4];
            float s = v.x + v.y + v.z + v.w;
            s += __shfl_xor_sync(0xffffffffu, s, 1);
            s += __shfl_xor_sync(0xffffffffu, s, 2);
            s += __shfl_xor_sync(0xffffffffu, s, 4);
            s += __shfl_xor_sync(0xffffffffu, s, 8);
            rs[it] += s;
        }
    }

    float inv[8];
#pragma unroll
    for (int i = 0; i < 8; i++) inv[i] = 1.0f / rs[i];

    wmma::fragment<wmma::accumulator, 16, 16, 16, float> c_o[2][2];
#pragma unroll
    for (int i = 0; i < 2; i++)
#pragma unroll
        for (int j = 0; j < 2; j++) wmma::fill_fragment(c_o[i][j], 0.f);

    __syncthreads();

    // ================= PASS 2: normalized P + PV =================
#pragma unroll
    for (int it = 0; it < 2; it++) {
        int row = crow + 32 * it;
        cpasync16(smb + KB_BOFF + row * 144 + cc * 16,
                  Kb + (size_t)row * D_ + cc * 8);
        cpasync16(smb + VB_BOFF + row * 144 + cc * 16,
                  Vb + (size_t)row * D_ + cc * 8);
    }
    cpasync_commit();

    for (int kc = 0; kc < 32; kc++) {
        const int cur = kc & 1;
        __half* Kc = (__half*)(smc + KB_BOFF + cur * KV_BSTRIDE);
        __half* Vc = (__half*)(smc + VB_BOFF + cur * KV_BSTRIDE);

        cpasync_wait0();
        __syncthreads();

        if (kc + 1 < 32) {
            const int nxt = 1 - cur;
#pragma unroll
            for (int it = 0; it < 2; it++) {
                int row = crow + 32 * it;
                cpasync16(smb + KB_BOFF + nxt * KV_BSTRIDE + row * 144 + cc * 16,
                          Kb + (size_t)((kc + 1) * 64 + row) * D_ + cc * 8);
                cpasync16(smb + VB_BOFF + nxt * KV_BSTRIDE + row * 144 + cc * 16,
                          Vb + (size_t)((kc + 1) * 64 + row) * D_ + cc * 8);
            }
            cpasync_commit();
        }

        wmma::fragment<wmma::accumulator, 16, 16, 16, float> c_s[2][2];
#pragma unroll
        for (int i = 0; i < 2; i++)
#pragma unroll
            for (int j = 0; j < 2; j++) wmma::fill_fragment(c_s[i][j], 0.f);
#pragma unroll
        for (int ks = 0; ks < 4; ks++) {
            wmma::fragment<wmma::matrix_b, 16, 16, 16, __half, wmma::col_major> bb[2];
#pragma unroll
            for (int j = 0; j < 2; j++)
                wmma::load_matrix_sync(bb[j], &Kc[(32 * wn + 16 * j) * 72 + ks * 16], 72);
#pragma unroll
            for (int i = 0; i < 2; i++)
#pragma unroll
                for (int j = 0; j < 2; j++)
                    wmma::mma_sync(c_s[i][j], Qf[ks][i], bb[j], c_s[i][j]);
        }

#pragma unroll
        for (int i = 0; i < 2; i++)
#pragma unroll
            for (int j = 0; j < 2; j++) {
#pragma unroll
                for (int e = 0; e < c_s[i][j].num_elements; e++)
                    c_s[i][j].x[e] = __expf(c_s[i][j].x[e]);
                wmma::store_matrix_sync(&Sst[(32 * wm + 16 * i) * 72 + 32 * wn + 16 * j],
                                        c_s[i][j], 72, wmma::mem_row_major);
            }
        __syncthreads();

        // staging pass: normalize, write fp32 P once, half PsH for PV
#pragma unroll
        for (int it = 0; it < 8; it++) {
            int row = prow + 16 * it;
            float4 v = *(float4*)&Sst[row * 72 + pc4 * 4];
            const float iv = inv[it];
            v.x *= iv; v.y *= iv; v.z *= iv; v.w *= iv;
            *(float4*)(Pb + (size_t)(q0 + row) * S_ + kc * 64 + pc4 * 4) = v;
            half2 h0 = __floats2half2_rn(v.x, v.y);
            half2 h1 = __floats2half2_rn(v.z, v.w);
            uint2 pk; pk.x = *(uint32_t*)&h0; pk.y = *(uint32_t*)&h1;
            *(uint2*)&PsH[row * 72 + pc4 * 4] = pk;
        }
        __syncthreads();

        // O += PsH(128x64) @ Vc(64x64)
#pragma unroll
        for (int ks = 0; ks < 4; ks++) {
            wmma::fragment<wmma::matrix_a, 16, 16, 16, __half, wmma::row_major> a2[2];
            wmma::fragment<wmma::matrix_b, 16, 16, 16, __half, wmma::row_major> b2[2];
#pragma unroll
            for (int i = 0; i < 2; i++)
                wmma::load_matrix_sync(a2[i], &PsH[(32 * wm + 16 * i) * 72 + ks * 16], 72);
#pragma unroll
            for (int j = 0; j < 2; j++)
                wmma::load_matrix_sync(b2[j], &Vc[(ks * 16) * 72 + 32 * wn + 16 * j], 72);
#pragma unroll
            for (int i = 0; i < 2; i++)
#pragma unroll
                for (int j = 0; j < 2; j++)
                    wmma::mma_sync(c_o[i][j], a2[i], b2[j], c_o[i][j]);
        }
    }

    // ---- O frags (already normalized) -> stage -> AO (half) ----
#pragma unroll
    for (int i = 0; i < 2; i++)
#pragma unroll
        for (int j = 0; j < 2; j++)
            wmma::store_matrix_sync(&Sst[(32 * wm + 16 * i) * 72 + 32 * wn + 16 * j],
                                    c_o[i][j], 72, wmma::mem_row_major);
    __syncthreads();

#pragma unroll
    for (int it = 0; it < 8; it++) {
        int row = prow + 16 * it;
        float4 v = *(float4*)&Sst[row * 72 + pc4 * 4];
        half2 h0 = __floats2half2_rn(v.x, v.y);
        half2 h1 = __floats2half2_rn(v.z, v.w);
        uint2 pk; pk.x = *(uint32_t*)&h0; pk.y = *(uint32_t*)&h1;
        *(uint2*)(AO + ((size_t)b * S_ + q0 + row) * D_ + h * DK_ + pc4 * 4) = pk;
    }
}

// ---------------------------------------------------------------------------
extern "C" void kernel_launch(void* const* d_in, const int* in_sizes, int n_in,
                              void* d_out, int out_size)
{
    const float* query = (const float*)d_in[0];
    const float* key_  = (const float*)d_in[1];
    const float* value = (const float*)d_in[2];
    const float* Wq = (const float*)d_in[3];
    const float* bq = (const float*)d_in[4];
    const float* Wk = (const float*)d_in[5];
    const float* bk = (const float*)d_in[6];
    const float* Wv = (const float*)d_in[7];
    const float* bv = (const float*)d_in[8];
    const float* Wo = (const float*)d_in[9];
    const float* bo = (const float*)d_in[10];

    float* out  = (float*)d_out;
    float* attn = out + (size_t)B_ * S_ * D_;

    __half *Xq, *Xk, *Xv, *Wh, *Qh, *Kh, *Vh, *AOh;
    cudaGetSymbolAddress((void**)&Xq,  g_Xq);
    cudaGetSymbolAddress((void**)&Xk,  g_Xk);
    cudaGetSymbolAddress((void**)&Xv,  g_Xv);
    cudaGetSymbolAddress((void**)&Wh,  g_Wh);
    cudaGetSymbolAddress((void**)&Qh,  g_Qh);
    cudaGetSymbolAddress((void**)&Kh,  g_Kh);
    cudaGetSymbolAddress((void**)&Vh,  g_Vh);
    cudaGetSymbolAddress((void**)&AOh, g_AOh);

    cudaFuncSetAttribute(fused_attn16,
                         cudaFuncAttributeMaxDynamicSharedMemorySize, FA_SMEM_BYTES);
    cudaFuncSetAttribute(qkv16,
                         cudaFuncAttributeMaxDynamicSharedMemorySize, G16_SMEM_BYTES);
    cudaFuncSetAttribute(out16,
                         cudaFuncAttributeMaxDynamicSharedMemorySize, G16_SMEM_BYTES);

    const int NB = (size_t)B_ * S_ * D_ / 4;   // 2.1M float4
    const int NW = D_ * D_ / 4;
    tohalf<<<2048, 256>>>(query, Xq, NB);
    tohalf<<<2048, 256>>>(key_,  Xk, NB);
    tohalf<<<2048, 256>>>(value, Xv, NB);
    tohalf<<<512, 256>>>(Wq, Wh + 0 * (size_t)D_ * D_, NW);
    tohalf<<<512, 256>>>(Wk, Wh + 1 * (size_t)D_ * D_, NW);
    tohalf<<<512, 256>>>(Wv, Wh + 2 * (size_t)D_ * D_, NW);
    tohalf<<<512, 256>>>(Wo, Wh + 3 * (size_t)D_ * D_, NW);

    qkv16<<<dim3(8, 64, 3), 256, G16_SMEM_BYTES>>>(
        Xq, Xk, Xv,
        Wh + 0 * (size_t)D_ * D_, bq,
        Wh + 1 * (size_t)D_ * D_, bk,
        Wh + 2 * (size_t)D_ * D_, bv,
        Qh, Kh, Vh);

    fused_attn16<<<dim3(16, 64), 256, FA_SMEM_BYTES>>>(Qh, Kh, Vh, attn, AOh);

    out16<<<dim3(8, 64), 256, G16_SMEM_BYTES>>>(AOh, Wh + 3 * (size_t)D_ * D_, bo, out);
}

// round 13
// speedup vs baseline: 3.2998x; 1.0850x over previous
#include <cuda_runtime.h>
#include <mma.h>
#include <cuda_fp16.h>
#include <cstdint>

using namespace nvcuda;

#define B_  4
#define S_  2048
#define D_  1024
#define H_  16
#define DK_ 64

// Scratch (__device__ globals; no allocs allowed).
__device__ __half g_Xq[(size_t)B_*S_*D_];
__device__ __half g_Xk[(size_t)B_*S_*D_];
__device__ __half g_Xv[(size_t)B_*S_*D_];
__device__ __half g_Wh[4][(size_t)D_*D_];
__device__ __half g_Qh[(size_t)B_*S_*D_];   // Qproj * 0.125
__device__ __half g_Kh[(size_t)B_*S_*D_];
__device__ __half g_Vh[(size_t)B_*S_*D_];
__device__ __half g_AOh[(size_t)B_*S_*D_];

__device__ __forceinline__ void cpasync16(uint32_t saddr, const void* g) {
    asm volatile("cp.async.cg.shared.global [%0], [%1], 16;" :: "r"(saddr), "l"(g));
}
__device__ __forceinline__ void cpasync_commit() {
    asm volatile("cp.async.commit_group;");
}
__device__ __forceinline__ void cpasync_wait0() {
    asm volatile("cp.async.wait_group 0;");
}

// ---------------------------------------------------------------------------
// fp32 -> fp16 conversion, all 7 tensors in one launch (z picks tensor).
// ---------------------------------------------------------------------------
__global__ __launch_bounds__(256) void tohalf_all(
    const float* __restrict__ q,  const float* __restrict__ k,
    const float* __restrict__ v,
    const float* __restrict__ wq, const float* __restrict__ wk,
    const float* __restrict__ wv, const float* __restrict__ wo,
    __half* __restrict__ xq, __half* __restrict__ xk, __half* __restrict__ xv,
    __half* __restrict__ wh)
{
    const int z = blockIdx.y;
    const float* in; __half* o; int n4;
    const int NB = (int)((size_t)B_ * S_ * D_ / 4);
    const int NW = D_ * D_ / 4;
    if (z == 0)      { in = q;  o = xq; n4 = NB; }
    else if (z == 1) { in = k;  o = xk; n4 = NB; }
    else if (z == 2) { in = v;  o = xv; n4 = NB; }
    else if (z == 3) { in = wq; o = wh + 0 * (size_t)D_ * D_; n4 = NW; }
    else if (z == 4) { in = wk; o = wh + 1 * (size_t)D_ * D_; n4 = NW; }
    else if (z == 5) { in = wv; o = wh + 2 * (size_t)D_ * D_; n4 = NW; }
    else             { in = wo; o = wh + 3 * (size_t)D_ * D_; n4 = NW; }

    int i = blockIdx.x * 256 + threadIdx.x;
    int stride = gridDim.x * 256;
    for (; i < n4; i += stride) {
        float4 vv = ((const float4*)in)[i];
        half2 h0 = __floats2half2_rn(vv.x, vv.y);
        half2 h1 = __floats2half2_rn(vv.z, vv.w);
        uint2 pk; pk.x = *(uint32_t*)&h0; pk.y = *(uint32_t*)&h1;
        ((uint2*)o)[i] = pk;
    }
}

// ---------------------------------------------------------------------------
// fp16 NT GEMM (pre-converted inputs): C = A @ W^T + bias.
// BM=BN=128, BK=64, cp.async double-buffered, 256 thr, warp tile 64x32.
// mode 0: fp32 out. 1: half out. 2: half out * 0.125.
// ---------------------------------------------------------------------------
#define GB_BUF 18432
#define G16_SMEM_BYTES 83968

__device__ __forceinline__ void gemm16_body(
    const __half* __restrict__ A, const __half* __restrict__ W,
    const float* __restrict__ bias, float* __restrict__ Cf,
    __half* __restrict__ Ch, int mode, char* smc)
{
    const int tid = threadIdx.x;
    const int w = tid >> 5, lane = tid & 31;
    const int wm = w >> 2, wn = w & 3;
    const size_t m0 = (size_t)blockIdx.y * 128;
    const size_t n0 = (size_t)blockIdx.x * 128;
    const uint32_t smb = (uint32_t)__cvta_generic_to_shared(smc);
    const int crow = tid >> 1;
    const int cc0  = (tid & 1) * 4;

    wmma::fragment<wmma::accumulator, 16, 16, 16, float> c[4][2];
#pragma unroll
    for (int i = 0; i < 4; i++)
#pragma unroll
        for (int j = 0; j < 2; j++) wmma::fill_fragment(c[i][j], 0.f);

#pragma unroll
    for (int ch = 0; ch < 4; ch++) {
        cpasync16(smb + crow * 144 + (cc0 + ch) * 16,
                  A + (m0 + crow) * 1024 + (cc0 + ch) * 8);
        cpasync16(smb + 36864 + crow * 144 + (cc0 + ch) * 16,
                  W + (n0 + crow) * 1024 + (cc0 + ch) * 8);
    }
    cpasync_commit();

    for (int kb = 0; kb < 16; kb++) {
        const int cur = kb & 1;
        cpasync_wait0();
        __syncthreads();

        if (kb < 15) {
            const int nxt = 1 - cur;
            const int k0 = (kb + 1) * 64;
#pragma unroll
            for (int ch = 0; ch < 4; ch++) {
                cpasync16(smb + nxt * GB_BUF + crow * 144 + (cc0 + ch) * 16,
                          A + (m0 + crow) * 1024 + k0 + (cc0 + ch) * 8);
                cpasync16(smb + 36864 + nxt * GB_BUF + crow * 144 + (cc0 + ch) * 16,
                          W + (n0 + crow) * 1024 + k0 + (cc0 + ch) * 8);
            }
            cpasync_commit();
        }

        const __half* ah = (const __half*)(smc + cur * GB_BUF);
        const __half* bh = (const __half*)(smc + 36864 + cur * GB_BUF);
#pragma unroll
        for (int ks = 0; ks < 4; ks++) {
            wmma::fragment<wmma::matrix_a, 16, 16, 16, __half, wmma::row_major> a[4];
            wmma::fragment<wmma::matrix_b, 16, 16, 16, __half, wmma::col_major> b[2];
#pragma unroll
            for (int i = 0; i < 4; i++)
                wmma::load_matrix_sync(a[i], &ah[(64 * wm + 16 * i) * 72 + ks * 16], 72);
#pragma unroll
            for (int j = 0; j < 2; j++)
                wmma::load_matrix_sync(b[j], &bh[(32 * wn + 16 * j) * 72 + ks * 16], 72);
#pragma unroll
            for (int i = 0; i < 4; i++)
#pragma unroll
                for (int j = 0; j < 2; j++)
                    wmma::mma_sync(c[i][j], a[i], b[j], c[i][j]);
        }
    }

    float* buf = (float*)(smc + 73728) + w * 320;
#pragma unroll
    for (int i = 0; i < 4; i++) {
#pragma unroll
        for (int j = 0; j < 2; j++) {
            wmma::store_matrix_sync(buf, c[i][j], 20, wmma::mem_row_major);
            __syncwarp();
            const int rr = lane >> 1, ch = (lane & 1) * 8;
            const size_t gr = m0 + 64 * wm + 16 * i + rr;
            const size_t gc = n0 + 32 * wn + 16 * j + ch;
            float4 v0 = *(float4*)&buf[rr * 20 + ch];
            float4 v1 = *(float4*)&buf[rr * 20 + ch + 4];
            v0.x += bias[gc + 0]; v0.y += bias[gc + 1];
            v0.z += bias[gc + 2]; v0.w += bias[gc + 3];
            v1.x += bias[gc + 4]; v1.y += bias[gc + 5];
            v1.z += bias[gc + 6]; v1.w += bias[gc + 7];
            if (mode == 0) {
                *(float4*)(Cf + gr * 1024 + gc)     = v0;
                *(float4*)(Cf + gr * 1024 + gc + 4) = v1;
            } else {
                if (mode == 2) {
                    v0.x *= 0.125f; v0.y *= 0.125f; v0.z *= 0.125f; v0.w *= 0.125f;
                    v1.x *= 0.125f; v1.y *= 0.125f; v1.z *= 0.125f; v1.w *= 0.125f;
                }
                half2 h0 = __floats2half2_rn(v0.x, v0.y);
                half2 h1 = __floats2half2_rn(v0.z, v0.w);
                half2 h2 = __floats2half2_rn(v1.x, v1.y);
                half2 h3 = __floats2half2_rn(v1.z, v1.w);
                uint4 pk;
                pk.x = *(uint32_t*)&h0; pk.y = *(uint32_t*)&h1;
                pk.z = *(uint32_t*)&h2; pk.w = *(uint32_t*)&h3;
                *(uint4*)(Ch + gr * 1024 + gc) = pk;
            }
            __syncwarp();
        }
    }
}

__global__ __launch_bounds__(256) void qkv16(
    const __half* __restrict__ xq, const __half* __restrict__ xk,
    const __half* __restrict__ xv,
    const __half* __restrict__ wq, const float* __restrict__ bq,
    const __half* __restrict__ wk, const float* __restrict__ bk,
    const __half* __restrict__ wv, const float* __restrict__ bv,
    __half* __restrict__ Qo, __half* __restrict__ Ko, __half* __restrict__ Vo)
{
    extern __shared__ char smc[];
    const __half *A, *W; const float* bi; __half* C; int mode;
    if (blockIdx.z == 0)      { A = xq; W = wq; bi = bq; C = Qo; mode = 2; }
    else if (blockIdx.z == 1) { A = xk; W = wk; bi = bk; C = Ko; mode = 1; }
    else                      { A = xv; W = wv; bi = bv; C = Vo; mode = 1; }
    gemm16_body(A, W, bi, nullptr, C, mode, smc);
}

__global__ __launch_bounds__(256) void out16(
    const __half* __restrict__ A, const __half* __restrict__ W,
    const float* __restrict__ bi, float* __restrict__ C)
{
    extern __shared__ char smc[];
    gemm16_body(A, W, bi, C, nullptr, 0, smc);
}

// ---------------------------------------------------------------------------
// Fused attention, TWO-PASS. Pass 1 does rowsums entirely in fragments
// (m16n8k16 accumulator layout: elems {0,1,4,5} -> row lane>>2,
//  {2,3,6,7} -> row (lane>>2)+8; cols vary over lane&3 -> shfl_xor 1,2).
// Pass 2: S mma + exp, normalize in staging pass, single fp32 P write,
// fp16 PV (normalized) -> O normalized; AO half.
// Smem: Sst f32 128*72 @0, PsH half @36864, KB dbl @55296, VB dbl @73728.
// ---------------------------------------------------------------------------
#define FA_SMEM_BYTES 92160
#define KB_BOFF 55296
#define VB_BOFF 73728
#define KV_BSTRIDE 9216

__global__ __launch_bounds__(256, 2) void fused_attn16(
    const __half* __restrict__ Q, const __half* __restrict__ K,
    const __half* __restrict__ V, float* __restrict__ P,
    __half* __restrict__ AO)
{
    extern __shared__ char smc[];
    float*  Sst = (float*)smc;
    __half* PsH = (__half*)(smc + 36864);
    const uint32_t smb = (uint32_t)__cvta_generic_to_shared(smc);

    const int tid = threadIdx.x, w = tid >> 5, lane = tid & 31;
    const int wm = w >> 1, wn = w & 1;          // 4x2 warp grid, 32x32 tiles
    const int bh = blockIdx.y, b = bh >> 4, h = bh & 15;
    const int q0 = blockIdx.x * 128;
    const int prow = tid >> 4, pc4 = tid & 15;  // staging-pass mapping
    const int crow = tid >> 3, cc = tid & 7;    // K/V copy mapping
    const int frow = lane >> 2;                 // fragment row base

    const __half* Qb = Q + (size_t)b * S_ * D_ + h * DK_;
    const __half* Kb = K + (size_t)b * S_ * D_ + h * DK_;
    const __half* Vb = V + (size_t)b * S_ * D_ + h * DK_;
    float* Pb = P + (size_t)bh * S_ * S_;

    // ---- Stage Q tile into PsH, preload fragments ----
#pragma unroll
    for (int it = 0; it < 4; it++) {
        int idx = tid + 256 * it;
        int row = idx >> 3, c = idx & 7;
        *(uint4*)&PsH[row * 72 + c * 8] =
            *(const uint4*)(Qb + (size_t)(q0 + row) * D_ + c * 8);
    }
    __syncthreads();
    wmma::fragment<wmma::matrix_a, 16, 16, 16, __half, wmma::row_major> Qf[4][2];
#pragma unroll
    for (int ks = 0; ks < 4; ks++)
#pragma unroll
        for (int i = 0; i < 2; i++)
            wmma::load_matrix_sync(Qf[ks][i], &PsH[(32 * wm + 16 * i) * 72 + ks * 16], 72);
    __syncthreads();

    // per-lane fragment rowsum accumulators: [i][r half]
    float rs0[2] = {0.f, 0.f};   // rows 32wm + 16i + frow
    float rs1[2] = {0.f, 0.f};   // rows 32wm + 16i + frow + 8

    // ================= PASS 1: rowsums (no staging, 1 barrier/chunk) ======
#pragma unroll
    for (int it = 0; it < 2; it++) {
        int row = crow + 32 * it;
        cpasync16(smb + KB_BOFF + row * 144 + cc * 16,
                  Kb + (size_t)row * D_ + cc * 8);
    }
    cpasync_commit();

    for (int kc = 0; kc < 32; kc++) {
        const int cur = kc & 1;
        __half* Kc = (__half*)(smc + KB_BOFF + cur * KV_BSTRIDE);

        cpasync_wait0();
        __syncthreads();

        if (kc + 1 < 32) {
            const int nxt = 1 - cur;
#pragma unroll
            for (int it = 0; it < 2; it++) {
                int row = crow + 32 * it;
                cpasync16(smb + KB_BOFF + nxt * KV_BSTRIDE + row * 144 + cc * 16,
                          Kb + (size_t)((kc + 1) * 64 + row) * D_ + cc * 8);
            }
            cpasync_commit();
        }

        wmma::fragment<wmma::accumulator, 16, 16, 16, float> c_s[2][2];
#pragma unroll
        for (int i = 0; i < 2; i++)
#pragma unroll
            for (int j = 0; j < 2; j++) wmma::fill_fragment(c_s[i][j], 0.f);
#pragma unroll
        for (int ks = 0; ks < 4; ks++) {
            wmma::fragment<wmma::matrix_b, 16, 16, 16, __half, wmma::col_major> bb[2];
#pragma unroll
            for (int j = 0; j < 2; j++)
                wmma::load_matrix_sync(bb[j], &Kc[(32 * wn + 16 * j) * 72 + ks * 16], 72);
#pragma unroll
            for (int i = 0; i < 2; i++)
#pragma unroll
                for (int j = 0; j < 2; j++)
                    wmma::mma_sync(c_s[i][j], Qf[ks][i], bb[j], c_s[i][j]);
        }

        // exp + in-fragment rowsum
#pragma unroll
        for (int i = 0; i < 2; i++) {
            float s0 = 0.f, s1 = 0.f;
#pragma unroll
            for (int j = 0; j < 2; j++) {
#pragma unroll
                for (int e = 0; e < 8; e++)
                    c_s[i][j].x[e] = __expf(c_s[i][j].x[e]);
                s0 += c_s[i][j].x[0] + c_s[i][j].x[1]
                    + c_s[i][j].x[4] + c_s[i][j].x[5];
                s1 += c_s[i][j].x[2] + c_s[i][j].x[3]
                    + c_s[i][j].x[6] + c_s[i][j].x[7];
            }
            s0 += __shfl_xor_sync(0xffffffffu, s0, 1);
            s0 += __shfl_xor_sync(0xffffffffu, s0, 2);
            s1 += __shfl_xor_sync(0xffffffffu, s1, 1);
            s1 += __shfl_xor_sync(0xffffffffu, s1, 2);
            rs0[i] += s0;
            rs1[i] += s1;
        }
    }

    // ---- combine across wn warps via smem (Sst reused: part[2][128]) ----
    float* part = Sst;
    if ((lane & 3) == 0) {
#pragma unroll
        for (int i = 0; i < 2; i++) {
            part[wn * 128 + 32 * wm + 16 * i + frow]     = rs0[i];
            part[wn * 128 + 32 * wm + 16 * i + frow + 8] = rs1[i];
        }
    }
    __syncthreads();

    float inv[8];
#pragma unroll
    for (int it = 0; it < 8; it++) {
        int row = prow + 16 * it;
        inv[it] = 1.0f / (part[row] + part[128 + row]);
    }

    wmma::fragment<wmma::accumulator, 16, 16, 16, float> c_o[2][2];
#pragma unroll
    for (int i = 0; i < 2; i++)
#pragma unroll
        for (int j = 0; j < 2; j++) wmma::fill_fragment(c_o[i][j], 0.f);

    __syncthreads();   // everyone has read part before Sst is reused

    // ================= PASS 2: normalized P + PV =================
#pragma unroll
    for (int it = 0; it < 2; it++) {
        int row = crow + 32 * it;
        cpasync16(smb + KB_BOFF + row * 144 + cc * 16,
                  Kb + (size_t)row * D_ + cc * 8);
        cpasync16(smb + VB_BOFF + row * 144 + cc * 16,
                  Vb + (size_t)row * D_ + cc * 8);
    }
    cpasync_commit();

    for (int kc = 0; kc < 32; kc++) {
        const int cur = kc & 1;
        __half* Kc = (__half*)(smc + KB_BOFF + cur * KV_BSTRIDE);
        __half* Vc = (__half*)(smc + VB_BOFF + cur * KV_BSTRIDE);

        cpasync_wait0();
        __syncthreads();

        if (kc + 1 < 32) {
            const int nxt = 1 - cur;
#pragma unroll
            for (int it = 0; it < 2; it++) {
                int row = crow + 32 * it;
                cpasync16(smb + KB_BOFF + nxt * KV_BSTRIDE + row * 144 + cc * 16,
                          Kb + (size_t)((kc + 1) * 64 + row) * D_ + cc * 8);
                cpasync16(smb + VB_BOFF + nxt * KV_BSTRIDE + row * 144 + cc * 16,
                          Vb + (size_t)((kc + 1) * 64 + row) * D_ + cc * 8);
            }
            cpasync_commit();
        }

        wmma::fragment<wmma::accumulator, 16, 16, 16, float> c_s[2][2];
#pragma unroll
        for (int i = 0; i < 2; i++)
#pragma unroll
            for (int j = 0; j < 2; j++) wmma::fill_fragment(c_s[i][j], 0.f);
#pragma unroll
        for (int ks = 0; ks < 4; ks++) {
            wmma::fragment<wmma::matrix_b, 16, 16, 16, __half, wmma::col_major> bb[2];
#pragma unroll
            for (int j = 0; j < 2; j++)
                wmma::load_matrix_sync(bb[j], &Kc[(32 * wn + 16 * j) * 72 + ks * 16], 72);
#pragma unroll
            for (int i = 0; i < 2; i++)
#pragma unroll
                for (int j = 0; j < 2; j++)
                    wmma::mma_sync(c_s[i][j], Qf[ks][i], bb[j], c_s[i][j]);
        }

#pragma unroll
        for (int i = 0; i < 2; i++)
#pragma unroll
            for (int j = 0; j < 2; j++) {
#pragma unroll
                for (int e = 0; e < 8; e++)
                    c_s[i][j].x[e] = __expf(c_s[i][j].x[e]);
                wmma::store_matrix_sync(&Sst[(32 * wm + 16 * i) * 72 + 32 * wn + 16 * j],
                                        c_s[i][j], 72, wmma::mem_row_major);
            }
        __syncthreads();

        // staging pass: normalize, write fp32 P once, half PsH for PV
#pragma unroll
        for (int it = 0; it < 8; it++) {
            int row = prow + 16 * it;
            float4 v = *(float4*)&Sst[row * 72 + pc4 * 4];
            const float iv = inv[it];
            v.x *= iv; v.y *= iv; v.z *= iv; v.w *= iv;
            *(float4*)(Pb + (size_t)(q0 + row) * S_ + kc * 64 + pc4 * 4) = v;
            half2 h0 = __floats2half2_rn(v.x, v.y);
            half2 h1 = __floats2half2_rn(v.z, v.w);
            uint2 pk; pk.x = *(uint32_t*)&h0; pk.y = *(uint32_t*)&h1;
            *(uint2*)&PsH[row * 72 + pc4 * 4] = pk;
        }
        __syncthreads();

        // O += PsH(128x64) @ Vc(64x64)
#pragma unroll
        for (int ks = 0; ks < 4; ks++) {
            wmma::fragment<wmma::matrix_a, 16, 16, 16, __half, wmma::row_major> a2[2];
            wmma::fragment<wmma::matrix_b, 16, 16, 16, __half, wmma::row_major> b2[2];
#pragma unroll
            for (int i = 0; i < 2; i++)
                wmma::load_matrix_sync(a2[i], &PsH[(32 * wm + 16 * i) * 72 + ks * 16], 72);
#pragma unroll
            for (int j = 0; j < 2; j++)
                wmma::load_matrix_sync(b2[j], &Vc[(ks * 16) * 72 + 32 * wn + 16 * j], 72);
#pragma unroll
            for (int i = 0; i < 2; i++)
#pragma unroll
                for (int j = 0; j < 2; j++)
                    wmma::mma_sync(c_o[i][j], a2[i], b2[j], c_o[i][j]);
        }
    }

    // ---- O frags (already normalized) -> stage -> AO (half) ----
#pragma unroll
    for (int i = 0; i < 2; i++)
#pragma unroll
        for (int j = 0; j < 2; j++)
            wmma::store_matrix_sync(&Sst[(32 * wm + 16 * i) * 72 + 32 * wn + 16 * j],
                                    c_o[i][j], 72, wmma::mem_row_major);
    __syncthreads();

#pragma unroll
    for (int it = 0; it < 8; it++) {
        int row = prow + 16 * it;
        float4 v = *(float4*)&Sst[row * 72 + pc4 * 4];
        half2 h0 = __floats2half2_rn(v.x, v.y);
        half2 h1 = __floats2half2_rn(v.z, v.w);
        uint2 pk; pk.x = *(uint32_t*)&h0; pk.y = *(uint32_t*)&h1;
        *(uint2*)(AO + ((size_t)b * S_ + q0 + row) * D_ + h * DK_ + pc4 * 4) = pk;
    }
}

// ---------------------------------------------------------------------------
extern "C" void kernel_launch(void* const* d_in, const int* in_sizes, int n_in,
                              void* d_out, int out_size)
{
    const float* query = (const float*)d_in[0];
    const float* key_  = (const float*)d_in[1];
    const float* value = (const float*)d_in[2];
    const float* Wq = (const float*)d_in[3];
    const float* bq = (const float*)d_in[4];
    const float* Wk = (const float*)d_in[5];
    const float* bk = (const float*)d_in[6];
    const float* Wv = (const float*)d_in[7];
    const float* bv = (const float*)d_in[8];
    const float* Wo = (const float*)d_in[9];
    const float* bo = (const float*)d_in[10];

    float* out  = (float*)d_out;
    float* attn = out + (size_t)B_ * S_ * D_;

    __half *Xq, *Xk, *Xv, *Wh, *Qh, *Kh, *Vh, *AOh;
    cudaGetSymbolAddress((void**)&Xq,  g_Xq);
    cudaGetSymbolAddress((void**)&Xk,  g_Xk);
    cudaGetSymbolAddress((void**)&Xv,  g_Xv);
    cudaGetSymbolAddress((void**)&Wh,  g_Wh);
    cudaGetSymbolAddress((void**)&Qh,  g_Qh);
    cudaGetSymbolAddress((void**)&Kh,  g_Kh);
    cudaGetSymbolAddress((void**)&Vh,  g_Vh);
    cudaGetSymbolAddress((void**)&AOh, g_AOh);

    cudaFuncSetAttribute(fused_attn16,
                         cudaFuncAttributeMaxDynamicSharedMemorySize, FA_SMEM_BYTES);
    cudaFuncSetAttribute(qkv16,
                         cudaFuncAttributeMaxDynamicSharedMemorySize, G16_SMEM_BYTES);
    cudaFuncSetAttribute(out16,
                         cudaFuncAttributeMaxDynamicSharedMemorySize, G16_SMEM_BYTES);

    tohalf_all<<<dim3(1024, 7), 256>>>(query, key_, value, Wq, Wk, Wv, Wo,
                                       Xq, Xk, Xv, Wh);

    qkv16<<<dim3(8, 64, 3), 256, G16_SMEM_BYTES>>>(
        Xq, Xk, Xv,
        Wh + 0 * (size_t)D_ * D_, bq,
        Wh + 1 * (size_t)D_ * D_, bk,
        Wh + 2 * (size_t)D_ * D_, bv,
        Qh, Kh, Vh);

    fused_attn16<<<dim3(16, 64), 256, FA_SMEM_BYTES>>>(Qh, Kh, Vh, attn, AOh);

    out16<<<dim3(8, 64), 256, G16_SMEM_BYTES>>>(AOh, Wh + 3 * (size_t)D_ * D_, bo, out);
}

// round 14
// speedup vs baseline: 3.9676x; 1.2024x over previous
#include <cuda_runtime.h>
#include <mma.h>
#include <cuda_fp16.h>
#include <cstdint>

using namespace nvcuda;

#define B_  4
#define S_  2048
#define D_  1024
#define H_  16
#define DK_ 64

// Scratch (__device__ globals; no allocs allowed).
__device__ __half g_Xq[(size_t)B_*S_*D_];
__device__ __half g_Xk[(size_t)B_*S_*D_];
__device__ __half g_Xv[(size_t)B_*S_*D_];
__device__ __half g_Wh[4][(size_t)D_*D_];
__device__ __half g_Qh[(size_t)B_*S_*D_];   // Qproj * 0.125
__device__ __half g_Kh[(size_t)B_*S_*D_];
__device__ __half g_Vh[(size_t)B_*S_*D_];
__device__ __half g_AOh[(size_t)B_*S_*D_];

__device__ __forceinline__ void cpasync16(uint32_t saddr, const void* g) {
    asm volatile("cp.async.cg.shared.global [%0], [%1], 16;" :: "r"(saddr), "l"(g));
}
__device__ __forceinline__ void cpasync_commit() {
    asm volatile("cp.async.commit_group;");
}
__device__ __forceinline__ void cpasync_wait0() {
    asm volatile("cp.async.wait_group 0;");
}

// ---------------------------------------------------------------------------
// fp32 -> fp16 conversion, all 7 tensors in one launch.
// ---------------------------------------------------------------------------
__global__ __launch_bounds__(256) void tohalf_all(
    const float* __restrict__ q,  const float* __restrict__ k,
    const float* __restrict__ v,
    const float* __restrict__ wq, const float* __restrict__ wk,
    const float* __restrict__ wv, const float* __restrict__ wo,
    __half* __restrict__ xq, __half* __restrict__ xk, __half* __restrict__ xv,
    __half* __restrict__ wh)
{
    const int z = blockIdx.y;
    const float* in; __half* o; int n4;
    const int NB = (int)((size_t)B_ * S_ * D_ / 4);
    const int NW = D_ * D_ / 4;
    if (z == 0)      { in = q;  o = xq; n4 = NB; }
    else if (z == 1) { in = k;  o = xk; n4 = NB; }
    else if (z == 2) { in = v;  o = xv; n4 = NB; }
    else if (z == 3) { in = wq; o = wh + 0 * (size_t)D_ * D_; n4 = NW; }
    else if (z == 4) { in = wk; o = wh + 1 * (size_t)D_ * D_; n4 = NW; }
    else if (z == 5) { in = wv; o = wh + 2 * (size_t)D_ * D_; n4 = NW; }
    else             { in = wo; o = wh + 3 * (size_t)D_ * D_; n4 = NW; }

    int i = blockIdx.x * 256 + threadIdx.x;
    int stride = gridDim.x * 256;
    for (; i < n4; i += stride) {
        float4 vv = ((const float4*)in)[i];
        half2 h0 = __floats2half2_rn(vv.x, vv.y);
        half2 h1 = __floats2half2_rn(vv.z, vv.w);
        uint2 pk; pk.x = *(uint32_t*)&h0; pk.y = *(uint32_t*)&h1;
        ((uint2*)o)[i] = pk;
    }
}

// ---------------------------------------------------------------------------
// fp16 NT GEMM, BM=64 / BN=128 / BK=64, 3 CTAs/SM for latency hiding.
// 8 warps (2 x 4), warp tile 32x32. cp.async double-buffered.
// mode 0: fp32 out. 1: half out. 2: half out * 0.125.
// Smem: A0 @0 (9216), A1 @9216, B0 @18432 (18432), B1 @36864, Cs @55296.
// ---------------------------------------------------------------------------
#define GA_BUF 9216
#define GB_BUF 18432
#define GB_BASE 18432
#define GCS_BASE 55296
#define G16_SMEM_BYTES 65536

__device__ __forceinline__ void gemm16_body(
    const __half* __restrict__ A, const __half* __restrict__ W,
    const float* __restrict__ bias, float* __restrict__ Cf,
    __half* __restrict__ Ch, int mode, char* smc)
{
    const int tid = threadIdx.x;
    const int w = tid >> 5, lane = tid & 31;
    const int wm = w >> 2, wn = w & 3;         // 2 x 4 warp grid
    const size_t m0 = (size_t)blockIdx.y * 64;
    const size_t n0 = (size_t)blockIdx.x * 128;
    const uint32_t smb = (uint32_t)__cvta_generic_to_shared(smc);
    const int crow = tid >> 3, cc = tid & 7;   // row, 16B-chunk

    wmma::fragment<wmma::accumulator, 16, 16, 16, float> c[2][2];
#pragma unroll
    for (int i = 0; i < 2; i++)
#pragma unroll
        for (int j = 0; j < 2; j++) wmma::fill_fragment(c[i][j], 0.f);

    // prologue: slab 0.  A: 64x8 chunks (2/thr), B: 128x8 chunks (4/thr)
#pragma unroll
    for (int it = 0; it < 2; it++) {
        int row = crow + 32 * it;
        cpasync16(smb + row * 144 + cc * 16,
                  A + (m0 + row) * 1024 + cc * 8);
    }
#pragma unroll
    for (int it = 0; it < 4; it++) {
        int row = crow + 32 * it;
        cpasync16(smb + GB_BASE + row * 144 + cc * 16,
                  W + (n0 + row) * 1024 + cc * 8);
    }
    cpasync_commit();

    for (int kb = 0; kb < 16; kb++) {
        const int cur = kb & 1;
        cpasync_wait0();
        __syncthreads();

        if (kb < 15) {
            const int nxt = 1 - cur;
            const int k0 = (kb + 1) * 64;
#pragma unroll
            for (int it = 0; it < 2; it++) {
                int row = crow + 32 * it;
                cpasync16(smb + nxt * GA_BUF + row * 144 + cc * 16,
                          A + (m0 + row) * 1024 + k0 + cc * 8);
            }
#pragma unroll
            for (int it = 0; it < 4; it++) {
                int row = crow + 32 * it;
                cpasync16(smb + GB_BASE + nxt * GB_BUF + row * 144 + cc * 16,
                          W + (n0 + row) * 1024 + k0 + cc * 8);
            }
            cpasync_commit();
        }

        const __half* ah = (const __half*)(smc + cur * GA_BUF);
        const __half* bh = (const __half*)(smc + GB_BASE + cur * GB_BUF);
#pragma unroll
        for (int ks = 0; ks < 4; ks++) {
            wmma::fragment<wmma::matrix_a, 16, 16, 16, __half, wmma::row_major> a[2];
            wmma::fragment<wmma::matrix_b, 16, 16, 16, __half, wmma::col_major> b[2];
#pragma unroll
            for (int i = 0; i < 2; i++)
                wmma::load_matrix_sync(a[i], &ah[(32 * wm + 16 * i) * 72 + ks * 16], 72);
#pragma unroll
            for (int j = 0; j < 2; j++)
                wmma::load_matrix_sync(b[j], &bh[(32 * wn + 16 * j) * 72 + ks * 16], 72);
#pragma unroll
            for (int i = 0; i < 2; i++)
#pragma unroll
                for (int j = 0; j < 2; j++)
                    wmma::mma_sync(c[i][j], a[i], b[j], c[i][j]);
        }
    }

    float* buf = (float*)(smc + GCS_BASE) + w * 320;
#pragma unroll
    for (int i = 0; i < 2; i++) {
#pragma unroll
        for (int j = 0; j < 2; j++) {
            wmma::store_matrix_sync(buf, c[i][j], 20, wmma::mem_row_major);
            __syncwarp();
            const int rr = lane >> 1, ch = (lane & 1) * 8;
            const size_t gr = m0 + 32 * wm + 16 * i + rr;
            const size_t gc = n0 + 32 * wn + 16 * j + ch;
            float4 v0 = *(float4*)&buf[rr * 20 + ch];
            float4 v1 = *(float4*)&buf[rr * 20 + ch + 4];
            v0.x += bias[gc + 0]; v0.y += bias[gc + 1];
            v0.z += bias[gc + 2]; v0.w += bias[gc + 3];
            v1.x += bias[gc + 4]; v1.y += bias[gc + 5];
            v1.z += bias[gc + 6]; v1.w += bias[gc + 7];
            if (mode == 0) {
                *(float4*)(Cf + gr * 1024 + gc)     = v0;
                *(float4*)(Cf + gr * 1024 + gc + 4) = v1;
            } else {
                if (mode == 2) {
                    v0.x *= 0.125f; v0.y *= 0.125f; v0.z *= 0.125f; v0.w *= 0.125f;
                    v1.x *= 0.125f; v1.y *= 0.125f; v1.z *= 0.125f; v1.w *= 0.125f;
                }
                half2 h0 = __floats2half2_rn(v0.x, v0.y);
                half2 h1 = __floats2half2_rn(v0.z, v0.w);
                half2 h2 = __floats2half2_rn(v1.x, v1.y);
                half2 h3 = __floats2half2_rn(v1.z, v1.w);
                uint4 pk;
                pk.x = *(uint32_t*)&h0; pk.y = *(uint32_t*)&h1;
                pk.z = *(uint32_t*)&h2; pk.w = *(uint32_t*)&h3;
                *(uint4*)(Ch + gr * 1024 + gc) = pk;
            }
            __syncwarp();
        }
    }
}

__global__ __launch_bounds__(256, 3) void qkv16(
    const __half* __restrict__ xq, const __half* __restrict__ xk,
    const __half* __restrict__ xv,
    const __half* __restrict__ wq, const float* __restrict__ bq,
    const __half* __restrict__ wk, const float* __restrict__ bk,
    const __half* __restrict__ wv, const float* __restrict__ bv,
    __half* __restrict__ Qo, __half* __restrict__ Ko, __half* __restrict__ Vo)
{
    extern __shared__ char smc[];
    const __half *A, *W; const float* bi; __half* C; int mode;
    if (blockIdx.z == 0)      { A = xq; W = wq; bi = bq; C = Qo; mode = 2; }
    else if (blockIdx.z == 1) { A = xk; W = wk; bi = bk; C = Ko; mode = 1; }
    else                      { A = xv; W = wv; bi = bv; C = Vo; mode = 1; }
    gemm16_body(A, W, bi, nullptr, C, mode, smc);
}

__global__ __launch_bounds__(256, 3) void out16(
    const __half* __restrict__ A, const __half* __restrict__ W,
    const float* __restrict__ bi, float* __restrict__ C)
{
    extern __shared__ char smc[];
    gemm16_body(A, W, bi, C, nullptr, 0, smc);
}

// ---------------------------------------------------------------------------
// Fused attention, TWO-PASS. Pass 1: in-fragment rowsums (1 barrier/chunk).
// Pass 2: per-warp OWN-REGION staging (syncwarp between frag store and
// staging; 2 barriers/chunk), inv preloaded per (lane, it).
// Smem: Sst f32 128*72 @0, PsH half @36864, KB dbl @55296, VB dbl @73728.
// ---------------------------------------------------------------------------
#define FA_SMEM_BYTES 92160
#define KB_BOFF 55296
#define VB_BOFF 73728
#define KV_BSTRIDE 9216

__global__ __launch_bounds__(256, 2) void fused_attn16(
    const __half* __restrict__ Q, const __half* __restrict__ K,
    const __half* __restrict__ V, float* __restrict__ P,
    __half* __restrict__ AO)
{
    extern __shared__ char smc[];
    float*  Sst = (float*)smc;
    __half* PsH = (__half*)(smc + 36864);
    const uint32_t smb = (uint32_t)__cvta_generic_to_shared(smc);

    const int tid = threadIdx.x, w = tid >> 5, lane = tid & 31;
    const int wm = w >> 1, wn = w & 1;          // 4x2 warp grid, 32x32 tiles
    const int bh = blockIdx.y, b = bh >> 4, h = bh & 15;
    const int q0 = blockIdx.x * 128;
    const int prow = tid >> 4, pc4 = tid & 15;  // block-wide pass mapping
    const int crow = tid >> 3, cc = tid & 7;    // K/V copy mapping
    const int frow = lane >> 2;                 // fragment row base
    const int srow = lane >> 3, sc4 = lane & 7; // own-region staging mapping

    const __half* Qb = Q + (size_t)b * S_ * D_ + h * DK_;
    const __half* Kb = K + (size_t)b * S_ * D_ + h * DK_;
    const __half* Vb = V + (size_t)b * S_ * D_ + h * DK_;
    float* Pb = P + (size_t)bh * S_ * S_;

    // ---- Stage Q tile into PsH, preload fragments ----
#pragma unroll
    for (int it = 0; it < 4; it++) {
        int idx = tid + 256 * it;
        int row = idx >> 3, c = idx & 7;
        *(uint4*)&PsH[row * 72 + c * 8] =
            *(const uint4*)(Qb + (size_t)(q0 + row) * D_ + c * 8);
    }
    __syncthreads();
    wmma::fragment<wmma::matrix_a, 16, 16, 16, __half, wmma::row_major> Qf[4][2];
#pragma unroll
    for (int ks = 0; ks < 4; ks++)
#pragma unroll
        for (int i = 0; i < 2; i++)
            wmma::load_matrix_sync(Qf[ks][i], &PsH[(32 * wm + 16 * i) * 72 + ks * 16], 72);
    __syncthreads();

    float rs0[2] = {0.f, 0.f};
    float rs1[2] = {0.f, 0.f};

    // ================= PASS 1: rowsums =================
#pragma unroll
    for (int it = 0; it < 2; it++) {
        int row = crow + 32 * it;
        cpasync16(smb + KB_BOFF + row * 144 + cc * 16,
                  Kb + (size_t)row * D_ + cc * 8);
    }
    cpasync_commit();

    for (int kc = 0; kc < 32; kc++) {
        const int cur = kc & 1;
        __half* Kc = (__half*)(smc + KB_BOFF + cur * KV_BSTRIDE);

        cpasync_wait0();
        __syncthreads();

        if (kc + 1 < 32) {
            const int nxt = 1 - cur;
#pragma unroll
            for (int it = 0; it < 2; it++) {
                int row = crow + 32 * it;
                cpasync16(smb + KB_BOFF + nxt * KV_BSTRIDE + row * 144 + cc * 16,
                          Kb + (size_t)((kc + 1) * 64 + row) * D_ + cc * 8);
            }
            cpasync_commit();
        }

        wmma::fragment<wmma::accumulator, 16, 16, 16, float> c_s[2][2];
#pragma unroll
        for (int i = 0; i < 2; i++)
#pragma unroll
            for (int j = 0; j < 2; j++) wmma::fill_fragment(c_s[i][j], 0.f);
#pragma unroll
        for (int ks = 0; ks < 4; ks++) {
            wmma::fragment<wmma::matrix_b, 16, 16, 16, __half, wmma::col_major> bb[2];
#pragma unroll
            for (int j = 0; j < 2; j++)
                wmma::load_matrix_sync(bb[j], &Kc[(32 * wn + 16 * j) * 72 + ks * 16], 72);
#pragma unroll
            for (int i = 0; i < 2; i++)
#pragma unroll
                for (int j = 0; j < 2; j++)
                    wmma::mma_sync(c_s[i][j], Qf[ks][i], bb[j], c_s[i][j]);
        }

#pragma unroll
        for (int i = 0; i < 2; i++) {
            float s0 = 0.f, s1 = 0.f;
#pragma unroll
            for (int j = 0; j < 2; j++) {
#pragma unroll
                for (int e = 0; e < 8; e++)
                    c_s[i][j].x[e] = __expf(c_s[i][j].x[e]);
                s0 += c_s[i][j].x[0] + c_s[i][j].x[1]
                    + c_s[i][j].x[4] + c_s[i][j].x[5];
                s1 += c_s[i][j].x[2] + c_s[i][j].x[3]
                    + c_s[i][j].x[6] + c_s[i][j].x[7];
            }
            s0 += __shfl_xor_sync(0xffffffffu, s0, 1);
            s0 += __shfl_xor_sync(0xffffffffu, s0, 2);
            s1 += __shfl_xor_sync(0xffffffffu, s1, 1);
            s1 += __shfl_xor_sync(0xffffffffu, s1, 2);
            rs0[i] += s0;
            rs1[i] += s1;
        }
    }

    // ---- combine across wn warps via smem (Sst reused: part[2][128]) ----
    float* part = Sst;
    if ((lane & 3) == 0) {
#pragma unroll
        for (int i = 0; i < 2; i++) {
            part[wn * 128 + 32 * wm + 16 * i + frow]     = rs0[i];
            part[wn * 128 + 32 * wm + 16 * i + frow + 8] = rs1[i];
        }
    }
    __syncthreads();

    // inv for own-region staging rows: row = 32wm + 4it + srow
    float invr[8];
#pragma unroll
    for (int it = 0; it < 8; it++) {
        int row = 32 * wm + 4 * it + srow;
        invr[it] = 1.0f / (part[row] + part[128 + row]);
    }

    wmma::fragment<wmma::accumulator, 16, 16, 16, float> c_o[2][2];
#pragma unroll
    for (int i = 0; i < 2; i++)
#pragma unroll
        for (int j = 0; j < 2; j++) wmma::fill_fragment(c_o[i][j], 0.f);

    __syncthreads();   // part consumed before Sst reuse

    // ================= PASS 2: normalized P + PV =================
#pragma unroll
    for (int it = 0; it < 2; it++) {
        int row = crow + 32 * it;
        cpasync16(smb + KB_BOFF + row * 144 + cc * 16,
                  Kb + (size_t)row * D_ + cc * 8);
        cpasync16(smb + VB_BOFF + row * 144 + cc * 16,
                  Vb + (size_t)row * D_ + cc * 8);
    }
    cpasync_commit();

    for (int kc = 0; kc < 32; kc++) {
        const int cur = kc & 1;
        __half* Kc = (__half*)(smc + KB_BOFF + cur * KV_BSTRIDE);
        __half* Vc = (__half*)(smc + VB_BOFF + cur * KV_BSTRIDE);

        cpasync_wait0();
        __syncthreads();

        if (kc + 1 < 32) {
            const int nxt = 1 - cur;
#pragma unroll
            for (int it = 0; it < 2; it++) {
                int row = crow + 32 * it;
                cpasync16(smb + KB_BOFF + nxt * KV_BSTRIDE + row * 144 + cc * 16,
                          Kb + (size_t)((kc + 1) * 64 + row) * D_ + cc * 8);
                cpasync16(smb + VB_BOFF + nxt * KV_BSTRIDE + row * 144 + cc * 16,
                          Vb + (size_t)((kc + 1) * 64 + row) * D_ + cc * 8);
            }
            cpasync_commit();
        }

        wmma::fragment<wmma::accumulator, 16, 16, 16, float> c_s[2][2];
#pragma unroll
        for (int i = 0; i < 2; i++)
#pragma unroll
            for (int j = 0; j < 2; j++) wmma::fill_fragment(c_s[i][j], 0.f);
#pragma unroll
        for (int ks = 0; ks < 4; ks++) {
            wmma::fragment<wmma::matrix_b, 16, 16, 16, __half, wmma::col_major> bb[2];
#pragma unroll
            for (int j = 0; j < 2; j++)
                wmma::load_matrix_sync(bb[j], &Kc[(32 * wn + 16 * j) * 72 + ks * 16], 72);
#pragma unroll
            for (int i = 0; i < 2; i++)
#pragma unroll
                for (int j = 0; j < 2; j++)
                    wmma::mma_sync(c_s[i][j], Qf[ks][i], bb[j], c_s[i][j]);
        }

        // exp in frags, store to OWN 32x32 region of Sst
#pragma unroll
        for (int i = 0; i < 2; i++)
#pragma unroll
            for (int j = 0; j < 2; j++) {
#pragma unroll
                for (int e = 0; e < 8; e++)
                    c_s[i][j].x[e] = __expf(c_s[i][j].x[e]);
                wmma::store_matrix_sync(&Sst[(32 * wm + 16 * i) * 72 + 32 * wn + 16 * j],
                                        c_s[i][j], 72, wmma::mem_row_major);
            }
        __syncwarp();

        // own-region staging: normalize, write fp32 P, half PsH
#pragma unroll
        for (int it = 0; it < 8; it++) {
            const int row = 32 * wm + 4 * it + srow;
            const int col = 32 * wn + sc4 * 4;
            float4 v = *(float4*)&Sst[row * 72 + col];
            const float iv = invr[it];
            v.x *= iv; v.y *= iv; v.z *= iv; v.w *= iv;
            *(float4*)(Pb + (size_t)(q0 + row) * S_ + kc * 64 + col) = v;
            half2 h0 = __floats2half2_rn(v.x, v.y);
            half2 h1 = __floats2half2_rn(v.z, v.w);
            uint2 pk; pk.x = *(uint32_t*)&h0; pk.y = *(uint32_t*)&h1;
            *(uint2*)&PsH[row * 72 + col] = pk;
        }
        __syncthreads();   // PsH complete across warps

        // O += PsH(128x64) @ Vc(64x64)
#pragma unroll
        for (int ks = 0; ks < 4; ks++) {
            wmma::fragment<wmma::matrix_a, 16, 16, 16, __half, wmma::row_major> a2[2];
            wmma::fragment<wmma::matrix_b, 16, 16, 16, __half, wmma::row_major> b2[2];
#pragma unroll
            for (int i = 0; i < 2; i++)
                wmma::load_matrix_sync(a2[i], &PsH[(32 * wm + 16 * i) * 72 + ks * 16], 72);
#pragma unroll
            for (int j = 0; j < 2; j++)
                wmma::load_matrix_sync(b2[j], &Vc[(ks * 16) * 72 + 32 * wn + 16 * j], 72);
#pragma unroll
            for (int i = 0; i < 2; i++)
#pragma unroll
                for (int j = 0; j < 2; j++)
                    wmma::mma_sync(c_o[i][j], a2[i], b2[j], c_o[i][j]);
        }
    }

    // ---- O frags (normalized P => normalized O) -> stage -> AO (half) ----
    __syncthreads();
#pragma unroll
    for (int i = 0; i < 2; i++)
#pragma unroll
        for (int j = 0; j < 2; j++)
            wmma::store_matrix_sync(&Sst[(32 * wm + 16 * i) * 72 + 32 * wn + 16 * j],
                                    c_o[i][j], 72, wmma::mem_row_major);
    __syncthreads();

#pragma unroll
    for (int it = 0; it < 8; it++) {
        int row = prow + 16 * it;
        float4 v = *(float4*)&Sst[row * 72 + pc4 * 4];
        half2 h0 = __floats2half2_rn(v.x, v.y);
        half2 h1 = __floats2half2_rn(v.z, v.w);
        uint2 pk; pk.x = *(uint32_t*)&h0; pk.y = *(uint32_t*)&h1;
        *(uint2*)(AO + ((size_t)b * S_ + q0 + row) * D_ + h * DK_ + pc4 * 4) = pk;
    }
}

// ---------------------------------------------------------------------------
extern "C" void kernel_launch(void* const* d_in, const int* in_sizes, int n_in,
                              void* d_out, int out_size)
{
    const float* query = (const float*)d_in[0];
    const float* key_  = (const float*)d_in[1];
    const float* value = (const float*)d_in[2];
    const float* Wq = (const float*)d_in[3];
    const float* bq = (const float*)d_in[4];
    const float* Wk = (const float*)d_in[5];
    const float* bk = (const float*)d_in[6];
    const float* Wv = (const float*)d_in[7];
    const float* bv = (const float*)d_in[8];
    const float* Wo = (const float*)d_in[9];
    const float* bo = (const float*)d_in[10];

    float* out  = (float*)d_out;
    float* attn = out + (size_t)B_ * S_ * D_;

    __half *Xq, *Xk, *Xv, *Wh, *Qh, *Kh, *Vh, *AOh;
    cudaGetSymbolAddress((void**)&Xq,  g_Xq);
    cudaGetSymbolAddress((void**)&Xk,  g_Xk);
    cudaGetSymbolAddress((void**)&Xv,  g_Xv);
    cudaGetSymbolAddress((void**)&Wh,  g_Wh);
    cudaGetSymbolAddress((void**)&Qh,  g_Qh);
    cudaGetSymbolAddress((void**)&Kh,  g_Kh);
    cudaGetSymbolAddress((void**)&Vh,  g_Vh);
    cudaGetSymbolAddress((void**)&AOh, g_AOh);

    cudaFuncSetAttribute(fused_attn16,
                         cudaFuncAttributeMaxDynamicSharedMemorySize, FA_SMEM_BYTES);
    cudaFuncSetAttribute(qkv16,
                         cudaFuncAttributeMaxDynamicSharedMemorySize, G16_SMEM_BYTES);
    cudaFuncSetAttribute(out16,
                         cudaFuncAttributeMaxDynamicSharedMemorySize, G16_SMEM_BYTES);

    tohalf_all<<<dim3(1024, 7), 256>>>(query, key_, value, Wq, Wk, Wv, Wo,
                                       Xq, Xk, Xv, Wh);

    qkv16<<<dim3(8, 128, 3), 256, G16_SMEM_BYTES>>>(
        Xq, Xk, Xv,
        Wh + 0 * (size_t)D_ * D_, bq,
        Wh + 1 * (size_t)D_ * D_, bk,
        Wh + 2 * (size_t)D_ * D_, bv,
        Qh, Kh, Vh);

    fused_attn16<<<dim3(16, 64), 256, FA_SMEM_BYTES>>>(Qh, Kh, Vh, attn, AOh);

    out16<<<dim3(8, 128), 256, G16_SMEM_BYTES>>>(AOh, Wh + 3 * (size_t)D_ * D_, bo, out);
}